// round 10
// baseline (speedup 1.0000x reference)
#include <cuda_runtime.h>
#include <cuda_fp16.h>

#define NN 100000
#define CAP 96

// ---------------------------------------------------------------------------
// Scratch (device globals — no allocation allowed)
// ---------------------------------------------------------------------------
__device__ __align__(16) __half g_yh[2][NN * 16];   // x @ w_nbr (fp16 payload)
__device__ __align__(16) float g_a1i[2][NN * 16];   // x @ w_self + b (init)
__device__ __align__(16) __half g_h1h[2][NN * 16];  // relu(agg1) fp16
__device__ __align__(16) float4 g_wst[1500];        // transposed w_in [60][25] f4
__device__ __align__(16) unsigned long long g_wsi2[2][800];  // (w2s,w2n) packed
__device__ __align__(16) int g_cnt[2][NN];          // per-node in-degree / cursor
__device__ __align__(16) int g_bkt[2][NN * CAP];    // src ids bucketed by dst

// ---------------------------------------------------------------------------
// packed f32x2 helpers
// ---------------------------------------------------------------------------
static __device__ __forceinline__ unsigned long long pk2(float x, float y) {
    unsigned long long r;
    asm("mov.b64 %0, {%1,%2};" : "=l"(r) : "f"(x), "f"(y));
    return r;
}
static __device__ __forceinline__ float2 upk2(unsigned long long v) {
    float2 r;
    asm("mov.b64 {%0,%1}, %2;" : "=f"(r.x), "=f"(r.y) : "l"(v));
    return r;
}
static __device__ __forceinline__ unsigned long long fma2(
    unsigned long long a, unsigned long long b, unsigned long long c) {
    unsigned long long d;
    asm("fma.rn.f32x2 %0, %1, %2, %3;" : "=l"(d) : "l"(a), "l"(b), "l"(c));
    return d;
}

// ---------------------------------------------------------------------------
// Prep (CSR stream): zero in-degree tables + pack/transpose small weights.
// ---------------------------------------------------------------------------
__global__ void prep_kernel(const float* __restrict__ w_in,
                            const float* __restrict__ wp2s, const float* __restrict__ wp2n,
                            const float* __restrict__ wl2s, const float* __restrict__ wl2n) {
    int i = blockIdx.x * 256 + threadIdx.x;
    if (i < (2 * NN) / 4) ((int4*)g_cnt)[i] = make_int4(0, 0, 0, 0);
    if (i < 1500) {
        int o = i / 25, kk = i % 25;
        float4 v;
        v.x = w_in[(kk * 4 + 0) * 60 + o];
        v.y = w_in[(kk * 4 + 1) * 60 + o];
        v.z = w_in[(kk * 4 + 2) * 60 + o];
        v.w = w_in[(kk * 4 + 3) * 60 + o];
        g_wst[i] = v;
    } else if (i < 2300) {
        int j = i - 1500;
        g_wsi2[0][j] = pk2(wp2s[j], wp2n[j]);
    } else if (i < 3100) {
        int j = i - 2300;
        g_wsi2[1][j] = pk2(wl2s[j], wl2n[j]);
    }
}

// ---------------------------------------------------------------------------
// Bucket build (single edge pass): slot = cnt[dst]++; bkt[dst][slot] = src.
// ---------------------------------------------------------------------------
__global__ void bucket_kernel(const int* __restrict__ s0, const int* __restrict__ d0,
                              const int* __restrict__ s1, const int* __restrict__ d1,
                              int E0, int E1) {
    int b = blockIdx.y;
    const int* src = b ? s1 : s0;
    const int* dst = b ? d1 : d0;
    int E = b ? E1 : E0;
    int e = blockIdx.x * 256 + threadIdx.x;
    if (e >= E) return;
    int d = dst[e];
    int slot = atomicAdd(&g_cnt[b][d], 1);
    if (slot < CAP) g_bkt[b][(size_t)d * CAP + slot] = src[e];
}

// ---------------------------------------------------------------------------
// Layer-1 projection, register-blocked (unchanged from R9).
//   y    = x @ w_nbr  (outs 0..15, fp16)
//   agg1 = x @ w_self + b (outs 16..31, fp32 gather init)
// ---------------------------------------------------------------------------
__global__ void proj_kernel(const float* __restrict__ x0, const float* __restrict__ x1,
                            const float* __restrict__ ws0, const float* __restrict__ ws1,
                            const float* __restrict__ wn0, const float* __restrict__ wn1,
                            const float* __restrict__ bb0, const float* __restrict__ bb1,
                            int N) {
    extern __shared__ float sm[];
    float* xs = sm;             // [128][129]
    float* ws = sm + 128 * 129; // [128][32]
    int b = blockIdx.y;
    const float* x = b ? x1 : x0;
    const float* w_self = b ? ws1 : ws0;
    const float* w_nbr = b ? wn1 : wn0;
    const float* bias = b ? bb1 : bb0;
    int t = threadIdx.x;
    int row0 = blockIdx.x << 7;

    for (int i = t; i < 2048; i += 256) {
        int k = i >> 4, o = i & 15;
        ws[k * 32 + o] = w_nbr[i];
        ws[k * 32 + o + 16] = w_self[i];
    }
    const float4* x4 = (const float4*)x;
    for (int i = t; i < 4096; i += 256) {
        int r = i >> 5, c4 = i & 31;
        int row = row0 + r;
        float4 v = (row < N) ? x4[row * 32 + c4] : make_float4(0.f, 0.f, 0.f, 0.f);
        float* p = xs + r * 129 + c4 * 4;
        p[0] = v.x; p[1] = v.y; p[2] = v.z; p[3] = v.w;
    }
    __syncthreads();

    int og = t & 3;   // outs og*8 .. og*8+7
    int rg = t >> 2;  // rows 2rg, 2rg+1
    const float* xr0 = xs + (2 * rg) * 129;
    const float* xr1 = xs + (2 * rg + 1) * 129;
    const float* wp = ws + og * 8;

    unsigned long long a0 = 0, a1 = 0, a2 = 0, a3 = 0;
    unsigned long long a4 = 0, a5 = 0, a6 = 0, a7 = 0;
#pragma unroll 8
    for (int k = 0; k < 128; k++) {
        unsigned long long X0 = pk2(xr0[k], xr0[k]);
        unsigned long long X1 = pk2(xr1[k], xr1[k]);
        ulonglong2 wA = *(const ulonglong2*)(wp + k * 32);
        ulonglong2 wB = *(const ulonglong2*)(wp + k * 32 + 4);
        a0 = fma2(X0, wA.x, a0); a1 = fma2(X0, wA.y, a1);
        a2 = fma2(X0, wB.x, a2); a3 = fma2(X0, wB.y, a3);
        a4 = fma2(X1, wA.x, a4); a5 = fma2(X1, wA.y, a5);
        a6 = fma2(X1, wB.x, a6); a7 = fma2(X1, wB.y, a7);
    }

    int r0 = row0 + 2 * rg;
    int r1 = r0 + 1;
    if (og < 2) {  // y -> fp16
        int oy = og * 8;
#define EMIT_Y(ROW, A0, A1, A2, A3)                                          \
        if ((ROW) < N) {                                                     \
            float2 p0 = upk2(A0), p1 = upk2(A1), p2 = upk2(A2), p3 = upk2(A3);\
            __half2 h0 = __floats2half2_rn(p0.x, p0.y);                      \
            __half2 h1 = __floats2half2_rn(p1.x, p1.y);                      \
            __half2 h2 = __floats2half2_rn(p2.x, p2.y);                      \
            __half2 h3 = __floats2half2_rn(p3.x, p3.y);                      \
            uint4 hv;                                                        \
            hv.x = *(unsigned*)&h0; hv.y = *(unsigned*)&h1;                  \
            hv.z = *(unsigned*)&h2; hv.w = *(unsigned*)&h3;                  \
            *(uint4*)(g_yh[b] + (ROW) * 16 + oy) = hv;                       \
        }
        EMIT_Y(r0, a0, a1, a2, a3)
        EMIT_Y(r1, a4, a5, a6, a7)
#undef EMIT_Y
    } else {  // agg1 init = self + bias -> fp32
        int oa = og * 8 - 16;
        float4 b0 = *(const float4*)(bias + oa);
        float4 b1 = *(const float4*)(bias + oa + 4);
#define EMIT_A(ROW, A0, A1, A2, A3)                                          \
        if ((ROW) < N) {                                                     \
            float2 p0 = upk2(A0), p1 = upk2(A1), p2 = upk2(A2), p3 = upk2(A3);\
            float4 v0 = make_float4(p0.x + b0.x, p0.y + b0.y,                \
                                    p1.x + b0.z, p1.y + b0.w);               \
            float4 v1 = make_float4(p2.x + b1.x, p2.y + b1.y,                \
                                    p3.x + b1.z, p3.y + b1.w);               \
            *(float4*)(g_a1i[b] + (ROW) * 16 + oa) = v0;                     \
            *(float4*)(g_a1i[b] + (ROW) * 16 + oa + 4) = v1;                 \
        }
        EMIT_A(r0, a0, a1, a2, a3)
        EMIT_A(r1, a4, a5, a6, a7)
#undef EMIT_A
    }
}

// ---------------------------------------------------------------------------
// Gather pass 0: h1 = relu(a1i + sum y[nbr]) -> fp16.
// 2 lanes per node (16B halves), fp32 accumulation, unroll-by-2.
// ---------------------------------------------------------------------------
__global__ void gather0_kernel(int N) {
    int b = blockIdx.y;
    int t = threadIdx.x;
    int node = blockIdx.x * 128 + (t >> 1);
    if (node >= N) return;
    int h = t & 1;
    int cnt = g_cnt[b][node];
    if (cnt > CAP) cnt = CAP;
    const int* __restrict__ bkt = g_bkt[b] + (size_t)node * CAP;
    const __half* __restrict__ Y = g_yh[b];

    float2 c0 = make_float2(0.f, 0.f), c1 = c0, c2 = c0, c3 = c0;
    float2 d0 = c0, d1 = c0, d2 = c0, d3 = c0;
    int k = 0;
    for (; k + 1 < cnt; k += 2) {
        int sA = __ldg(bkt + k);
        int sB = __ldg(bkt + k + 1);
        uint4 rA = *(const uint4*)(Y + ((size_t)sA << 4) + (h << 3));
        uint4 rB = *(const uint4*)(Y + ((size_t)sB << 4) + (h << 3));
        float2 fA0 = __half22float2(*(const __half2*)&rA.x);
        float2 fA1 = __half22float2(*(const __half2*)&rA.y);
        float2 fA2 = __half22float2(*(const __half2*)&rA.z);
        float2 fA3 = __half22float2(*(const __half2*)&rA.w);
        float2 fB0 = __half22float2(*(const __half2*)&rB.x);
        float2 fB1 = __half22float2(*(const __half2*)&rB.y);
        float2 fB2 = __half22float2(*(const __half2*)&rB.z);
        float2 fB3 = __half22float2(*(const __half2*)&rB.w);
        c0.x += fA0.x; c0.y += fA0.y; c1.x += fA1.x; c1.y += fA1.y;
        c2.x += fA2.x; c2.y += fA2.y; c3.x += fA3.x; c3.y += fA3.y;
        d0.x += fB0.x; d0.y += fB0.y; d1.x += fB1.x; d1.y += fB1.y;
        d2.x += fB2.x; d2.y += fB2.y; d3.x += fB3.x; d3.y += fB3.y;
    }
    if (k < cnt) {
        int s = __ldg(bkt + k);
        uint4 raw = *(const uint4*)(Y + ((size_t)s << 4) + (h << 3));
        float2 f0 = __half22float2(*(const __half2*)&raw.x);
        float2 f1 = __half22float2(*(const __half2*)&raw.y);
        float2 f2 = __half22float2(*(const __half2*)&raw.z);
        float2 f3 = __half22float2(*(const __half2*)&raw.w);
        c0.x += f0.x; c0.y += f0.y; c1.x += f1.x; c1.y += f1.y;
        c2.x += f2.x; c2.y += f2.y; c3.x += f3.x; c3.y += f3.y;
    }
    c0.x += d0.x; c0.y += d0.y; c1.x += d1.x; c1.y += d1.y;
    c2.x += d2.x; c2.y += d2.y; c3.x += d3.x; c3.y += d3.y;

    size_t off = (size_t)node * 16 + (h << 3);
    const float4* ip = (const float4*)(g_a1i[b] + off);
    float4 i0 = ip[0], i1 = ip[1];
    __half2 q0 = __floats2half2_rn(fmaxf(c0.x + i0.x, 0.f), fmaxf(c0.y + i0.y, 0.f));
    __half2 q1 = __floats2half2_rn(fmaxf(c1.x + i0.z, 0.f), fmaxf(c1.y + i0.w, 0.f));
    __half2 q2 = __floats2half2_rn(fmaxf(c2.x + i1.x, 0.f), fmaxf(c2.y + i1.y, 0.f));
    __half2 q3 = __floats2half2_rn(fmaxf(c3.x + i1.z, 0.f), fmaxf(c3.y + i1.w, 0.f));
    uint4 hv;
    hv.x = *(unsigned*)&q0; hv.y = *(unsigned*)&q1;
    hv.z = *(unsigned*)&q2; hv.w = *(unsigned*)&q3;
    *(uint4*)(g_h1h[b] + off) = hv;
}

// ---------------------------------------------------------------------------
// Fused tail: gather pass 1 (agg2, in registers) + layer-2 convs + MLP head.
// One thread per row.
// ---------------------------------------------------------------------------
__global__ __launch_bounds__(128)
void tail_kernel(const float* __restrict__ action,
                 const float* __restrict__ bp2, const float* __restrict__ bl2,
                 const float* __restrict__ b_in, const float* __restrict__ w_hid,
                 const float* __restrict__ b_hid, const float* __restrict__ w_out,
                 const float* __restrict__ b_out, float* __restrict__ out, int N) {
    __shared__ __align__(16) unsigned long long wsi[2][800];
    __shared__ __align__(16) float4 wst[1500];
    __shared__ __align__(16) float wh[700];
    __shared__ float bi[60];
    __shared__ float bs2[2][50];
    __shared__ __align__(16) float bh[12];
    __shared__ float wo[10];
    __shared__ float bo;
    int t = threadIdx.x;
    for (int i = t; i < 800; i += 128) {
        wsi[0][i] = g_wsi2[0][i];
        wsi[1][i] = g_wsi2[1][i];
    }
    for (int i = t; i < 1500; i += 128) wst[i] = g_wst[i];
    for (int i = t; i < 700; i += 128) wh[i] = w_hid[i];
    if (t < 60) bi[t] = b_in[t];
    if (t < 50) { bs2[0][t] = bp2[t]; bs2[1][t] = bl2[t]; }
    if (t < 10) { bh[t] = b_hid[t]; wo[t] = w_out[t]; }
    if (t == 0) bo = b_out[0];
    __syncthreads();

    int row = blockIdx.x * 128 + t;
    if (row >= N) return;

    unsigned long long molp[50];
#pragma unroll
    for (int b = 0; b < 2; b++) {
        const __half* __restrict__ Y = g_h1h[b];
        const int* __restrict__ bkt = g_bkt[b] + (size_t)row * CAP;
        int cnt = g_cnt[b][row];
        if (cnt > CAP) cnt = CAP;

        // gather agg2 for this row into registers (fp32 accum over fp16 rows)
        float2 c0 = make_float2(0.f, 0.f), c1 = c0, c2 = c0, c3 = c0;
        float2 c4 = c0, c5 = c0, c6 = c0, c7 = c0;
        float2 e0 = c0, e1 = c0, e2 = c0, e3 = c0;
        float2 e4 = c0, e5 = c0, e6 = c0, e7 = c0;
        int k = 0;
        for (; k + 1 < cnt; k += 2) {
            int sA = __ldg(bkt + k);
            int sB = __ldg(bkt + k + 1);
            const uint4* pA = (const uint4*)(Y + ((size_t)sA << 4));
            const uint4* pB = (const uint4*)(Y + ((size_t)sB << 4));
            uint4 A0 = pA[0], A1 = pA[1];
            uint4 B0 = pB[0], B1 = pB[1];
#define ACC2(C, W)                                                           \
            { float2 f = __half22float2(*(const __half2*)&(W));              \
              C.x += f.x; C.y += f.y; }
            ACC2(c0, A0.x) ACC2(c1, A0.y) ACC2(c2, A0.z) ACC2(c3, A0.w)
            ACC2(c4, A1.x) ACC2(c5, A1.y) ACC2(c6, A1.z) ACC2(c7, A1.w)
            ACC2(e0, B0.x) ACC2(e1, B0.y) ACC2(e2, B0.z) ACC2(e3, B0.w)
            ACC2(e4, B1.x) ACC2(e5, B1.y) ACC2(e6, B1.z) ACC2(e7, B1.w)
        }
        if (k < cnt) {
            int s = __ldg(bkt + k);
            const uint4* p = (const uint4*)(Y + ((size_t)s << 4));
            uint4 A0 = p[0], A1 = p[1];
            ACC2(c0, A0.x) ACC2(c1, A0.y) ACC2(c2, A0.z) ACC2(c3, A0.w)
            ACC2(c4, A1.x) ACC2(c5, A1.y) ACC2(c6, A1.z) ACC2(c7, A1.w)
        }
#undef ACC2
        c0.x += e0.x; c0.y += e0.y; c1.x += e1.x; c1.y += e1.y;
        c2.x += e2.x; c2.y += e2.y; c3.x += e3.x; c3.y += e3.y;
        c4.x += e4.x; c4.y += e4.y; c5.x += e5.x; c5.y += e5.y;
        c6.x += e6.x; c6.y += e6.y; c7.x += e7.x; c7.y += e7.y;

        float ag[16];
        ag[0] = c0.x; ag[1] = c0.y; ag[2] = c1.x; ag[3] = c1.y;
        ag[4] = c2.x; ag[5] = c2.y; ag[6] = c3.x; ag[7] = c3.y;
        ag[8] = c4.x; ag[9] = c4.y; ag[10] = c5.x; ag[11] = c5.y;
        ag[12] = c6.x; ag[13] = c6.y; ag[14] = c7.x; ag[15] = c7.y;

        // own h1 row (fp16)
        float hv[16];
        {
            const uint4* hp = (const uint4*)(Y + ((size_t)row << 4));
            uint4 H0 = hp[0], H1 = hp[1];
            float2 f;
            f = __half22float2(*(const __half2*)&H0.x); hv[0] = f.x; hv[1] = f.y;
            f = __half22float2(*(const __half2*)&H0.y); hv[2] = f.x; hv[3] = f.y;
            f = __half22float2(*(const __half2*)&H0.z); hv[4] = f.x; hv[5] = f.y;
            f = __half22float2(*(const __half2*)&H0.w); hv[6] = f.x; hv[7] = f.y;
            f = __half22float2(*(const __half2*)&H1.x); hv[8] = f.x; hv[9] = f.y;
            f = __half22float2(*(const __half2*)&H1.y); hv[10] = f.x; hv[11] = f.y;
            f = __half22float2(*(const __half2*)&H1.z); hv[12] = f.x; hv[13] = f.y;
            f = __half22float2(*(const __half2*)&H1.w); hv[14] = f.x; hv[15] = f.y;
        }

        unsigned long long ha[16];
#pragma unroll
        for (int j = 0; j < 16; j++) ha[j] = pk2(hv[j], ag[j]);

        float prev = 0.f;
#pragma unroll 2
        for (int o = 0; o < 50; o++) {
            unsigned long long a0 = 0, a1 = 0;
#pragma unroll
            for (int kk = 0; kk < 16; kk += 2) {
                a0 = fma2(ha[kk], wsi[b][kk * 50 + o], a0);
                a1 = fma2(ha[kk + 1], wsi[b][(kk + 1) * 50 + o], a1);
            }
            float2 p = upk2(a0), q = upk2(a1);
            float m = bs2[b][o] + ((p.x + p.y) + (q.x + q.y));
            if (o & 1) molp[(b * 50 + o) >> 1] = pk2(prev, m);
            else prev = m;
        }
    }

    unsigned long long pol2[5];
    const unsigned long long* bh2 = (const unsigned long long*)bh;
#pragma unroll
    for (int a = 0; a < 5; a++) pol2[a] = bh2[a];

#pragma unroll 1
    for (int o = 0; o < 60; o++) {
        const ulonglong2* wr = (const ulonglong2*)(wst + o * 25);
        unsigned long long a0 = 0, a1 = 0;
#pragma unroll
        for (int kk = 0; kk < 25; kk++) {
            ulonglong2 wv = wr[kk];
            a0 = fma2(molp[2 * kk], wv.x, a0);
            a1 = fma2(molp[2 * kk + 1], wv.y, a1);
        }
        float2 p = upk2(a0), q = upk2(a1);
        float f = fmaxf(bi[o] + ((p.x + p.y) + (q.x + q.y)), 0.f);
        unsigned long long f2 = pk2(f, f);
        const unsigned long long* whp = (const unsigned long long*)(wh + o * 10);
#pragma unroll
        for (int a = 0; a < 5; a++) pol2[a] = fma2(f2, whp[a], pol2[a]);
    }

    const unsigned long long* a2 = (const unsigned long long*)(action + (size_t)row * 10);
#pragma unroll
    for (int jj = 0; jj < 5; jj++) {
        float2 ap = upk2(a2[jj]);
        unsigned long long u = pk2(ap.x, ap.x);
        unsigned long long v = pk2(ap.y, ap.y);
        const unsigned long long* w1 = (const unsigned long long*)(wh + (60 + 2 * jj) * 10);
        const unsigned long long* w2p = (const unsigned long long*)(wh + (61 + 2 * jj) * 10);
#pragma unroll
        for (int a = 0; a < 5; a++) {
            pol2[a] = fma2(u, w1[a], pol2[a]);
            pol2[a] = fma2(v, w2p[a], pol2[a]);
        }
    }

    float res = bo;
#pragma unroll
    for (int a = 0; a < 5; a++) {
        float2 p = upk2(pol2[a]);
        res = fmaf(fmaxf(p.x, 0.f), wo[2 * a], res);
        res = fmaf(fmaxf(p.y, 0.f), wo[2 * a + 1], res);
    }
    out[row] = res;
}

// ---------------------------------------------------------------------------
// Side stream + fork/join events (created once at load).
// ---------------------------------------------------------------------------
static cudaStream_t g_s1 = 0;
static cudaEvent_t g_evRoot = 0, g_evCsr = 0;
static bool g_forkOk = false;
namespace {
struct ForkInit {
    ForkInit() {
        bool ok = true;
        ok &= (cudaStreamCreateWithFlags(&g_s1, cudaStreamNonBlocking) == cudaSuccess);
        ok &= (cudaEventCreateWithFlags(&g_evRoot, cudaEventDisableTiming) == cudaSuccess);
        ok &= (cudaEventCreateWithFlags(&g_evCsr, cudaEventDisableTiming) == cudaSuccess);
        g_forkOk = ok;
    }
};
static ForkInit g_forkInit;
}  // namespace

// ---------------------------------------------------------------------------
extern "C" void kernel_launch(void* const* d_in, const int* in_sizes, int n_in,
                              void* d_out, int out_size) {
    const float* px = (const float*)d_in[0];
    const int*   pe = (const int*)d_in[1];
    const float* lx = (const float*)d_in[2];
    const int*   le = (const int*)d_in[3];
    const float* action = (const float*)d_in[4];
    const float* wp1s = (const float*)d_in[5];
    const float* wp1n = (const float*)d_in[6];
    const float* bp1  = (const float*)d_in[7];
    const float* wp2s = (const float*)d_in[8];
    const float* wp2n = (const float*)d_in[9];
    const float* bp2  = (const float*)d_in[10];
    const float* wl1s = (const float*)d_in[11];
    const float* wl1n = (const float*)d_in[12];
    const float* bl1  = (const float*)d_in[13];
    const float* wl2s = (const float*)d_in[14];
    const float* wl2n = (const float*)d_in[15];
    const float* bl2  = (const float*)d_in[16];
    const float* w_in  = (const float*)d_in[17];
    const float* b_in  = (const float*)d_in[18];
    const float* w_hid = (const float*)d_in[19];
    const float* b_hid = (const float*)d_in[20];
    const float* w_out = (const float*)d_in[21];
    const float* b_out = (const float*)d_in[22];
    float* out = (float*)d_out;

    int N = in_sizes[0] / 128;
    int E0 = in_sizes[1] / 2;
    int E1 = in_sizes[3] / 2;
    int Em = (E0 > E1) ? E0 : E1;

    cudaStream_t sc = g_forkOk ? g_s1 : (cudaStream_t)0;  // bucket-arm stream
    if (g_forkOk) {
        cudaEventRecord(g_evRoot, 0);
        cudaStreamWaitEvent(g_s1, g_evRoot, 0);
    }

    // ---- dense arm (capture stream) -------------------------------------
    const int proj_smem = (128 * 129 + 128 * 32) * (int)sizeof(float);
    cudaFuncSetAttribute(proj_kernel, cudaFuncAttributeMaxDynamicSharedMemorySize,
                         proj_smem);
    dim3 gp((N + 127) / 128, 2);
    proj_kernel<<<gp, 256, proj_smem>>>(px, lx, wp1s, wl1s, wp1n, wl1n, bp1, bl1, N);

    // ---- bucket arm (side stream) ----------------------------------------
    prep_kernel<<<((2 * NN / 4) + 255) / 256, 256, 0, sc>>>(w_in, wp2s, wp2n,
                                                            wl2s, wl2n);
    dim3 ge((Em + 255) / 256, 2);
    bucket_kernel<<<ge, 256, 0, sc>>>(pe, pe + E0, le, le + E1, E0, E1);

    if (g_forkOk) {
        cudaEventRecord(g_evCsr, g_s1);
        cudaStreamWaitEvent(0, g_evCsr, 0);
    }

    // ---- joined: gather pass 0, then fused tail ---------------------------
    dim3 gg((N + 127) / 128, 2);
    gather0_kernel<<<gg, 256>>>(N);

    tail_kernel<<<(N + 127) / 128, 128>>>(action, bp2, bl2, b_in, w_hid, b_hid,
                                          w_out, b_out, out, N);
}

// round 11
// speedup vs baseline: 1.1340x; 1.1340x over previous
#include <cuda_runtime.h>
#include <cuda_fp16.h>

#define NN 100000
#define CAP 96

// ---------------------------------------------------------------------------
// Scratch (device globals — no allocation allowed)
// ---------------------------------------------------------------------------
__device__ __align__(16) __half g_yh[2][NN * 16];   // x @ w_nbr (fp16 payload)
__device__ __align__(16) float g_a1i[2][NN * 16];   // x @ w_self + b (init)
__device__ __align__(16) float g_h1f[2][NN * 16];   // relu(agg1) fp32 (for tail)
__device__ __align__(16) __half g_h1h[2][NN * 16];  // relu(agg1) fp16 (payload)
__device__ __align__(16) float g_agg2[2][NN * 16];  // segsum(relu(agg1))
__device__ __align__(16) float4 g_wst[1500];        // transposed w_in [60][25] f4
__device__ __align__(16) unsigned long long g_wsi2[2][800];  // (w2s,w2n) packed
__device__ __align__(16) int g_cnt[2][NN];          // per-node in-degree
__device__ __align__(16) int g_bkt[2][NN * CAP];    // src ids bucketed by dst

// ---------------------------------------------------------------------------
// packed f32x2 helpers
// ---------------------------------------------------------------------------
static __device__ __forceinline__ unsigned long long pk2(float x, float y) {
    unsigned long long r;
    asm("mov.b64 %0, {%1,%2};" : "=l"(r) : "f"(x), "f"(y));
    return r;
}
static __device__ __forceinline__ float2 upk2(unsigned long long v) {
    float2 r;
    asm("mov.b64 {%0,%1}, %2;" : "=f"(r.x), "=f"(r.y) : "l"(v));
    return r;
}
static __device__ __forceinline__ unsigned long long fma2(
    unsigned long long a, unsigned long long b, unsigned long long c) {
    unsigned long long d;
    asm("fma.rn.f32x2 %0, %1, %2, %3;" : "=l"(d) : "l"(a), "l"(b), "l"(c));
    return d;
}

// ---------------------------------------------------------------------------
// Prep (side stream): zero in-degree tables + pack/transpose small weights.
// ---------------------------------------------------------------------------
__global__ void prep_kernel(const float* __restrict__ w_in,
                            const float* __restrict__ wp2s, const float* __restrict__ wp2n,
                            const float* __restrict__ wl2s, const float* __restrict__ wl2n) {
    int i = blockIdx.x * 256 + threadIdx.x;
    if (i < (2 * NN) / 4) ((int4*)g_cnt)[i] = make_int4(0, 0, 0, 0);
    if (i < 1500) {
        int o = i / 25, kk = i % 25;
        float4 v;
        v.x = w_in[(kk * 4 + 0) * 60 + o];
        v.y = w_in[(kk * 4 + 1) * 60 + o];
        v.z = w_in[(kk * 4 + 2) * 60 + o];
        v.w = w_in[(kk * 4 + 3) * 60 + o];
        g_wst[i] = v;
    } else if (i < 2300) {
        int j = i - 1500;
        g_wsi2[0][j] = pk2(wp2s[j], wp2n[j]);
    } else if (i < 3100) {
        int j = i - 2300;
        g_wsi2[1][j] = pk2(wl2s[j], wl2n[j]);
    }
}

// ---------------------------------------------------------------------------
// Bucket build (single edge pass): slot = cnt[dst]++; bkt[dst][slot] = src.
// ---------------------------------------------------------------------------
__global__ void bucket_kernel(const int* __restrict__ s0, const int* __restrict__ d0,
                              const int* __restrict__ s1, const int* __restrict__ d1,
                              int E0, int E1) {
    int b = blockIdx.y;
    const int* src = b ? s1 : s0;
    const int* dst = b ? d1 : d0;
    int E = b ? E1 : E0;
    int e = blockIdx.x * 256 + threadIdx.x;
    if (e >= E) return;
    int d = dst[e];
    int slot = atomicAdd(&g_cnt[b][d], 1);
    if (slot < CAP) g_bkt[b][(size_t)d * CAP + slot] = src[e];
}

// ---------------------------------------------------------------------------
// Layer-1 projection, register-blocked (unchanged).
//   y    = x @ w_nbr  (outs 0..15, fp16)
//   agg1 = x @ w_self + b (outs 16..31, fp32 gather init)
// ---------------------------------------------------------------------------
__global__ void proj_kernel(const float* __restrict__ x0, const float* __restrict__ x1,
                            const float* __restrict__ ws0, const float* __restrict__ ws1,
                            const float* __restrict__ wn0, const float* __restrict__ wn1,
                            const float* __restrict__ bb0, const float* __restrict__ bb1,
                            int N) {
    extern __shared__ float sm[];
    float* xs = sm;             // [128][129]
    float* ws = sm + 128 * 129; // [128][32]
    int b = blockIdx.y;
    const float* x = b ? x1 : x0;
    const float* w_self = b ? ws1 : ws0;
    const float* w_nbr = b ? wn1 : wn0;
    const float* bias = b ? bb1 : bb0;
    int t = threadIdx.x;
    int row0 = blockIdx.x << 7;

    for (int i = t; i < 2048; i += 256) {
        int k = i >> 4, o = i & 15;
        ws[k * 32 + o] = w_nbr[i];
        ws[k * 32 + o + 16] = w_self[i];
    }
    const float4* x4 = (const float4*)x;
    for (int i = t; i < 4096; i += 256) {
        int r = i >> 5, c4 = i & 31;
        int row = row0 + r;
        float4 v = (row < N) ? x4[row * 32 + c4] : make_float4(0.f, 0.f, 0.f, 0.f);
        float* p = xs + r * 129 + c4 * 4;
        p[0] = v.x; p[1] = v.y; p[2] = v.z; p[3] = v.w;
    }
    __syncthreads();

    int og = t & 3;   // outs og*8 .. og*8+7
    int rg = t >> 2;  // rows 2rg, 2rg+1
    const float* xr0 = xs + (2 * rg) * 129;
    const float* xr1 = xs + (2 * rg + 1) * 129;
    const float* wp = ws + og * 8;

    unsigned long long a0 = 0, a1 = 0, a2 = 0, a3 = 0;
    unsigned long long a4 = 0, a5 = 0, a6 = 0, a7 = 0;
#pragma unroll 8
    for (int k = 0; k < 128; k++) {
        unsigned long long X0 = pk2(xr0[k], xr0[k]);
        unsigned long long X1 = pk2(xr1[k], xr1[k]);
        ulonglong2 wA = *(const ulonglong2*)(wp + k * 32);
        ulonglong2 wB = *(const ulonglong2*)(wp + k * 32 + 4);
        a0 = fma2(X0, wA.x, a0); a1 = fma2(X0, wA.y, a1);
        a2 = fma2(X0, wB.x, a2); a3 = fma2(X0, wB.y, a3);
        a4 = fma2(X1, wA.x, a4); a5 = fma2(X1, wA.y, a5);
        a6 = fma2(X1, wB.x, a6); a7 = fma2(X1, wB.y, a7);
    }

    int r0 = row0 + 2 * rg;
    int r1 = r0 + 1;
    if (og < 2) {  // y -> fp16
        int oy = og * 8;
#define EMIT_Y(ROW, A0, A1, A2, A3)                                          \
        if ((ROW) < N) {                                                     \
            float2 p0 = upk2(A0), p1 = upk2(A1), p2 = upk2(A2), p3 = upk2(A3);\
            __half2 h0 = __floats2half2_rn(p0.x, p0.y);                      \
            __half2 h1 = __floats2half2_rn(p1.x, p1.y);                      \
            __half2 h2 = __floats2half2_rn(p2.x, p2.y);                      \
            __half2 h3 = __floats2half2_rn(p3.x, p3.y);                      \
            uint4 hv;                                                        \
            hv.x = *(unsigned*)&h0; hv.y = *(unsigned*)&h1;                  \
            hv.z = *(unsigned*)&h2; hv.w = *(unsigned*)&h3;                  \
            *(uint4*)(g_yh[b] + (ROW) * 16 + oy) = hv;                       \
        }
        EMIT_Y(r0, a0, a1, a2, a3)
        EMIT_Y(r1, a4, a5, a6, a7)
#undef EMIT_Y
    } else {  // agg1 init = self + bias -> fp32
        int oa = og * 8 - 16;
        float4 b0 = *(const float4*)(bias + oa);
        float4 b1 = *(const float4*)(bias + oa + 4);
#define EMIT_A(ROW, A0, A1, A2, A3)                                          \
        if ((ROW) < N) {                                                     \
            float2 p0 = upk2(A0), p1 = upk2(A1), p2 = upk2(A2), p3 = upk2(A3);\
            float4 v0 = make_float4(p0.x + b0.x, p0.y + b0.y,                \
                                    p1.x + b0.z, p1.y + b0.w);               \
            float4 v1 = make_float4(p2.x + b1.x, p2.y + b1.y,                \
                                    p3.x + b1.z, p3.y + b1.w);               \
            *(float4*)(g_a1i[b] + (ROW) * 16 + oa) = v0;                     \
            *(float4*)(g_a1i[b] + (ROW) * 16 + oa + 4) = v1;                 \
        }
        EMIT_A(r0, a0, a1, a2, a3)
        EMIT_A(r1, a4, a5, a6, a7)
#undef EMIT_A
    }
}

// ---------------------------------------------------------------------------
// Gather aggregation: 2 lanes per node (16B half-rows), int4 index loads
// (1 index instr per 4 edges), 4 payload loads in flight, dual accumulators.
// PASS 0: agg1 = a1i + sum y[nbr]; h1f = relu(agg1) fp32; h1h = fp16(h1f)
// PASS 1: agg2 = sum h1h[nbr]
// ---------------------------------------------------------------------------
template <int PASS>
__global__ void gather_kernel(int N) {
    int b = blockIdx.y;
    int t = threadIdx.x;
    int node = blockIdx.x * 128 + (t >> 1);
    if (node >= N) return;
    int h = t & 1;
    int cnt = g_cnt[b][node];
    if (cnt > CAP) cnt = CAP;
    const int* __restrict__ bkt = g_bkt[b] + (size_t)node * CAP;
    const __half* __restrict__ Y = PASS ? g_h1h[b] : g_yh[b];

    float2 c0 = make_float2(0.f, 0.f), c1 = c0, c2 = c0, c3 = c0;
    float2 d0 = c0, d1 = c0, d2 = c0, d3 = c0;
#define ACC2(C, W)                                                           \
    { float2 f = __half22float2(*(const __half2*)&(W));                      \
      C.x += f.x; C.y += f.y; }

    int k = 0;
    for (; k + 3 < cnt; k += 4) {
        int4 s4 = *(const int4*)(bkt + k);
        uint4 rA = *(const uint4*)(Y + ((size_t)s4.x << 4) + (h << 3));
        uint4 rB = *(const uint4*)(Y + ((size_t)s4.y << 4) + (h << 3));
        uint4 rC = *(const uint4*)(Y + ((size_t)s4.z << 4) + (h << 3));
        uint4 rD = *(const uint4*)(Y + ((size_t)s4.w << 4) + (h << 3));
        ACC2(c0, rA.x) ACC2(c1, rA.y) ACC2(c2, rA.z) ACC2(c3, rA.w)
        ACC2(d0, rB.x) ACC2(d1, rB.y) ACC2(d2, rB.z) ACC2(d3, rB.w)
        ACC2(c0, rC.x) ACC2(c1, rC.y) ACC2(c2, rC.z) ACC2(c3, rC.w)
        ACC2(d0, rD.x) ACC2(d1, rD.y) ACC2(d2, rD.z) ACC2(d3, rD.w)
    }
    for (; k < cnt; k++) {
        int s = __ldg(bkt + k);
        uint4 raw = *(const uint4*)(Y + ((size_t)s << 4) + (h << 3));
        ACC2(c0, raw.x) ACC2(c1, raw.y) ACC2(c2, raw.z) ACC2(c3, raw.w)
    }
#undef ACC2
    c0.x += d0.x; c0.y += d0.y; c1.x += d1.x; c1.y += d1.y;
    c2.x += d2.x; c2.y += d2.y; c3.x += d3.x; c3.y += d3.y;

    size_t off = (size_t)node * 16 + (h << 3);
    if (PASS) {
        *(float4*)(g_agg2[b] + off) = make_float4(c0.x, c0.y, c1.x, c1.y);
        *(float4*)(g_agg2[b] + off + 4) = make_float4(c2.x, c2.y, c3.x, c3.y);
    } else {
        const float4* ip = (const float4*)(g_a1i[b] + off);
        float4 i0 = ip[0], i1 = ip[1];
        float4 v0 = make_float4(fmaxf(c0.x + i0.x, 0.f), fmaxf(c0.y + i0.y, 0.f),
                                fmaxf(c1.x + i0.z, 0.f), fmaxf(c1.y + i0.w, 0.f));
        float4 v1 = make_float4(fmaxf(c2.x + i1.x, 0.f), fmaxf(c2.y + i1.y, 0.f),
                                fmaxf(c3.x + i1.z, 0.f), fmaxf(c3.y + i1.w, 0.f));
        *(float4*)(g_h1f[b] + off) = v0;
        *(float4*)(g_h1f[b] + off + 4) = v1;
        __half2 q0 = __floats2half2_rn(v0.x, v0.y);
        __half2 q1 = __floats2half2_rn(v0.z, v0.w);
        __half2 q2 = __floats2half2_rn(v1.x, v1.y);
        __half2 q3 = __floats2half2_rn(v1.z, v1.w);
        uint4 hv;
        hv.x = *(unsigned*)&q0; hv.y = *(unsigned*)&q1;
        hv.z = *(unsigned*)&q2; hv.w = *(unsigned*)&q3;
        *(uint4*)(g_h1h[b] + off) = hv;
    }
}

// ---------------------------------------------------------------------------
// Fused tail: layer-2 convs (both branches) + MLP head, mol in registers.
// Streaming, coalesced reads of h1f/agg2 only — no random lines.
// ---------------------------------------------------------------------------
__global__ __launch_bounds__(128)
void tail_kernel(const float* __restrict__ action,
                 const float* __restrict__ bp2, const float* __restrict__ bl2,
                 const float* __restrict__ b_in, const float* __restrict__ w_hid,
                 const float* __restrict__ b_hid, const float* __restrict__ w_out,
                 const float* __restrict__ b_out, float* __restrict__ out, int N) {
    __shared__ __align__(16) unsigned long long wsi[2][800];
    __shared__ __align__(16) float4 wst[1500];
    __shared__ __align__(16) float wh[700];
    __shared__ float bi[60];
    __shared__ float bs2[2][50];
    __shared__ __align__(16) float bh[12];
    __shared__ float wo[10];
    __shared__ float bo;
    int t = threadIdx.x;
    for (int i = t; i < 800; i += 128) {
        wsi[0][i] = g_wsi2[0][i];
        wsi[1][i] = g_wsi2[1][i];
    }
    for (int i = t; i < 1500; i += 128) wst[i] = g_wst[i];
    for (int i = t; i < 700; i += 128) wh[i] = w_hid[i];
    if (t < 60) bi[t] = b_in[t];
    if (t < 50) { bs2[0][t] = bp2[t]; bs2[1][t] = bl2[t]; }
    if (t < 10) { bh[t] = b_hid[t]; wo[t] = w_out[t]; }
    if (t == 0) bo = b_out[0];
    __syncthreads();

    int row = blockIdx.x * 128 + t;
    if (row >= N) return;

    unsigned long long molp[50];
#pragma unroll
    for (int b = 0; b < 2; b++) {
        unsigned long long ha[16];
        const float4* hp = (const float4*)(g_h1f[b] + (size_t)row * 16);
        const float4* ap = (const float4*)(g_agg2[b] + (size_t)row * 16);
#pragma unroll
        for (int q = 0; q < 4; q++) {
            float4 hv = hp[q], av = ap[q];
            ha[q * 4 + 0] = pk2(hv.x, av.x);
            ha[q * 4 + 1] = pk2(hv.y, av.y);
            ha[q * 4 + 2] = pk2(hv.z, av.z);
            ha[q * 4 + 3] = pk2(hv.w, av.w);
        }
        float prev = 0.f;
#pragma unroll 2
        for (int o = 0; o < 50; o++) {
            unsigned long long a0 = 0, a1 = 0;
#pragma unroll
            for (int k = 0; k < 16; k += 2) {
                a0 = fma2(ha[k], wsi[b][k * 50 + o], a0);
                a1 = fma2(ha[k + 1], wsi[b][(k + 1) * 50 + o], a1);
            }
            float2 p = upk2(a0), q = upk2(a1);
            float m = bs2[b][o] + ((p.x + p.y) + (q.x + q.y));
            if (o & 1) molp[(b * 50 + o) >> 1] = pk2(prev, m);
            else prev = m;
        }
    }

    unsigned long long pol2[5];
    const unsigned long long* bh2 = (const unsigned long long*)bh;
#pragma unroll
    for (int a = 0; a < 5; a++) pol2[a] = bh2[a];

#pragma unroll 1
    for (int o = 0; o < 60; o++) {
        const ulonglong2* wr = (const ulonglong2*)(wst + o * 25);
        unsigned long long a0 = 0, a1 = 0;
#pragma unroll
        for (int kk = 0; kk < 25; kk++) {
            ulonglong2 wv = wr[kk];
            a0 = fma2(molp[2 * kk], wv.x, a0);
            a1 = fma2(molp[2 * kk + 1], wv.y, a1);
        }
        float2 p = upk2(a0), q = upk2(a1);
        float f = fmaxf(bi[o] + ((p.x + p.y) + (q.x + q.y)), 0.f);
        unsigned long long f2 = pk2(f, f);
        const unsigned long long* whp = (const unsigned long long*)(wh + o * 10);
#pragma unroll
        for (int a = 0; a < 5; a++) pol2[a] = fma2(f2, whp[a], pol2[a]);
    }

    const unsigned long long* a2 = (const unsigned long long*)(action + (size_t)row * 10);
#pragma unroll
    for (int jj = 0; jj < 5; jj++) {
        float2 ap = upk2(a2[jj]);
        unsigned long long u = pk2(ap.x, ap.x);
        unsigned long long v = pk2(ap.y, ap.y);
        const unsigned long long* w1 = (const unsigned long long*)(wh + (60 + 2 * jj) * 10);
        const unsigned long long* w2p = (const unsigned long long*)(wh + (61 + 2 * jj) * 10);
#pragma unroll
        for (int a = 0; a < 5; a++) {
            pol2[a] = fma2(u, w1[a], pol2[a]);
            pol2[a] = fma2(v, w2p[a], pol2[a]);
        }
    }

    float res = bo;
#pragma unroll
    for (int a = 0; a < 5; a++) {
        float2 p = upk2(pol2[a]);
        res = fmaf(fmaxf(p.x, 0.f), wo[2 * a], res);
        res = fmaf(fmaxf(p.y, 0.f), wo[2 * a + 1], res);
    }
    out[row] = res;
}

// ---------------------------------------------------------------------------
// Side stream + fork/join events (created once at load).
// ---------------------------------------------------------------------------
static cudaStream_t g_s1 = 0;
static cudaEvent_t g_evRoot = 0, g_evCsr = 0;
static bool g_forkOk = false;
namespace {
struct ForkInit {
    ForkInit() {
        bool ok = true;
        ok &= (cudaStreamCreateWithFlags(&g_s1, cudaStreamNonBlocking) == cudaSuccess);
        ok &= (cudaEventCreateWithFlags(&g_evRoot, cudaEventDisableTiming) == cudaSuccess);
        ok &= (cudaEventCreateWithFlags(&g_evCsr, cudaEventDisableTiming) == cudaSuccess);
        g_forkOk = ok;
    }
};
static ForkInit g_forkInit;
}  // namespace

// ---------------------------------------------------------------------------
extern "C" void kernel_launch(void* const* d_in, const int* in_sizes, int n_in,
                              void* d_out, int out_size) {
    const float* px = (const float*)d_in[0];
    const int*   pe = (const int*)d_in[1];
    const float* lx = (const float*)d_in[2];
    const int*   le = (const int*)d_in[3];
    const float* action = (const float*)d_in[4];
    const float* wp1s = (const float*)d_in[5];
    const float* wp1n = (const float*)d_in[6];
    const float* bp1  = (const float*)d_in[7];
    const float* wp2s = (const float*)d_in[8];
    const float* wp2n = (const float*)d_in[9];
    const float* bp2  = (const float*)d_in[10];
    const float* wl1s = (const float*)d_in[11];
    const float* wl1n = (const float*)d_in[12];
    const float* bl1  = (const float*)d_in[13];
    const float* wl2s = (const float*)d_in[14];
    const float* wl2n = (const float*)d_in[15];
    const float* bl2  = (const float*)d_in[16];
    const float* w_in  = (const float*)d_in[17];
    const float* b_in  = (const float*)d_in[18];
    const float* w_hid = (const float*)d_in[19];
    const float* b_hid = (const float*)d_in[20];
    const float* w_out = (const float*)d_in[21];
    const float* b_out = (const float*)d_in[22];
    float* out = (float*)d_out;

    int N = in_sizes[0] / 128;
    int E0 = in_sizes[1] / 2;
    int E1 = in_sizes[3] / 2;
    int Em = (E0 > E1) ? E0 : E1;

    cudaStream_t sc = g_forkOk ? g_s1 : (cudaStream_t)0;  // bucket-arm stream
    if (g_forkOk) {
        cudaEventRecord(g_evRoot, 0);
        cudaStreamWaitEvent(g_s1, g_evRoot, 0);
    }

    // ---- dense arm (capture stream) -------------------------------------
    const int proj_smem = (128 * 129 + 128 * 32) * (int)sizeof(float);
    cudaFuncSetAttribute(proj_kernel, cudaFuncAttributeMaxDynamicSharedMemorySize,
                         proj_smem);
    dim3 gp((N + 127) / 128, 2);
    proj_kernel<<<gp, 256, proj_smem>>>(px, lx, wp1s, wl1s, wp1n, wl1n, bp1, bl1, N);

    // ---- bucket arm (side stream) ----------------------------------------
    prep_kernel<<<((2 * NN / 4) + 255) / 256, 256, 0, sc>>>(w_in, wp2s, wp2n,
                                                            wl2s, wl2n);
    dim3 ge((Em + 255) / 256, 2);
    bucket_kernel<<<ge, 256, 0, sc>>>(pe, pe + E0, le, le + E1, E0, E1);

    if (g_forkOk) {
        cudaEventRecord(g_evCsr, g_s1);
        cudaStreamWaitEvent(0, g_evCsr, 0);
    }

    // ---- joined: gathers + tail (capture stream) -------------------------
    dim3 gg((N + 127) / 128, 2);
    gather_kernel<0><<<gg, 256>>>(N);
    gather_kernel<1><<<gg, 256>>>(N);

    tail_kernel<<<(N + 127) / 128, 128>>>(action, bp2, bl2, b_in, w_hid, b_hid,
                                          w_out, b_out, out, N);
}

// round 13
// speedup vs baseline: 1.1856x; 1.0455x over previous
#include <cuda_runtime.h>
#include <cuda_fp16.h>

#define NN 100000
#define CAP 96

// ---------------------------------------------------------------------------
// Scratch (device globals — no allocation allowed)
// ---------------------------------------------------------------------------
__device__ __align__(16) __half g_yh[2][NN * 16];   // x @ w_nbr (fp16 payload)
__device__ __align__(16) float g_a1i[2][NN * 16];   // x @ w_self + b (init)
__device__ __align__(16) float g_h1f[2][NN * 16];   // relu(agg1) fp32 (for tail)
__device__ __align__(16) __half g_h1h[2][NN * 16];  // relu(agg1) fp16 (payload)
__device__ __align__(16) float g_agg2[2][NN * 16];  // segsum(relu(agg1))
__device__ __align__(16) float4 g_wst[1500];        // transposed w_in [60][25] f4
__device__ __align__(16) unsigned long long g_wsi2[2][800];  // (w2s,w2n) packed
__device__ __align__(16) int g_cnt[2][NN];          // per-node in-degree
__device__ __align__(16) int g_bkt[2][NN * CAP];    // src ids bucketed by dst

// ---------------------------------------------------------------------------
// packed f32x2 / f16x2 helpers
// ---------------------------------------------------------------------------
static __device__ __forceinline__ unsigned long long pk2(float x, float y) {
    unsigned long long r;
    asm("mov.b64 %0, {%1,%2};" : "=l"(r) : "f"(x), "f"(y));
    return r;
}
static __device__ __forceinline__ float2 upk2(unsigned long long v) {
    float2 r;
    asm("mov.b64 {%0,%1}, %2;" : "=f"(r.x), "=f"(r.y) : "l"(v));
    return r;
}
static __device__ __forceinline__ unsigned long long fma2(
    unsigned long long a, unsigned long long b, unsigned long long c) {
    unsigned long long d;
    asm("fma.rn.f32x2 %0, %1, %2, %3;" : "=l"(d) : "l"(a), "l"(b), "l"(c));
    return d;
}
// fp16x2 add on raw 32-bit representation (nestable)
static __device__ __forceinline__ unsigned hadd2u(unsigned a, unsigned b) {
    unsigned r;
    asm("add.f16x2 %0, %1, %2;" : "=r"(r) : "r"(a), "r"(b));
    return r;
}
static __device__ __forceinline__ float2 h2f2(unsigned v) {
    return __half22float2(*(const __half2*)&v);
}

// ---------------------------------------------------------------------------
// Prep (side stream): zero in-degree tables + pack/transpose small weights.
// ---------------------------------------------------------------------------
__global__ void prep_kernel(const float* __restrict__ w_in,
                            const float* __restrict__ wp2s, const float* __restrict__ wp2n,
                            const float* __restrict__ wl2s, const float* __restrict__ wl2n) {
    int i = blockIdx.x * 256 + threadIdx.x;
    if (i < (2 * NN) / 4) ((int4*)g_cnt)[i] = make_int4(0, 0, 0, 0);
    if (i < 1500) {
        int o = i / 25, kk = i % 25;
        float4 v;
        v.x = w_in[(kk * 4 + 0) * 60 + o];
        v.y = w_in[(kk * 4 + 1) * 60 + o];
        v.z = w_in[(kk * 4 + 2) * 60 + o];
        v.w = w_in[(kk * 4 + 3) * 60 + o];
        g_wst[i] = v;
    } else if (i < 2300) {
        int j = i - 1500;
        g_wsi2[0][j] = pk2(wp2s[j], wp2n[j]);
    } else if (i < 3100) {
        int j = i - 2300;
        g_wsi2[1][j] = pk2(wl2s[j], wl2n[j]);
    }
}

// ---------------------------------------------------------------------------
// Bucket build (single edge pass): slot = cnt[dst]++; bkt[dst][slot] = src.
// ---------------------------------------------------------------------------
__global__ void bucket_kernel(const int* __restrict__ s0, const int* __restrict__ d0,
                              const int* __restrict__ s1, const int* __restrict__ d1,
                              int E0, int E1) {
    int b = blockIdx.y;
    const int* src = b ? s1 : s0;
    const int* dst = b ? d1 : d0;
    int E = b ? E1 : E0;
    int e = blockIdx.x * 256 + threadIdx.x;
    if (e >= E) return;
    int d = dst[e];
    int slot = atomicAdd(&g_cnt[b][d], 1);
    if (slot < CAP) g_bkt[b][(size_t)d * CAP + slot] = src[e];
}

// ---------------------------------------------------------------------------
// Layer-1 projection, register-blocked (unchanged).
// ---------------------------------------------------------------------------
__global__ void proj_kernel(const float* __restrict__ x0, const float* __restrict__ x1,
                            const float* __restrict__ ws0, const float* __restrict__ ws1,
                            const float* __restrict__ wn0, const float* __restrict__ wn1,
                            const float* __restrict__ bb0, const float* __restrict__ bb1,
                            int N) {
    extern __shared__ float sm[];
    float* xs = sm;             // [128][129]
    float* ws = sm + 128 * 129; // [128][32]
    int b = blockIdx.y;
    const float* x = b ? x1 : x0;
    const float* w_self = b ? ws1 : ws0;
    const float* w_nbr = b ? wn1 : wn0;
    const float* bias = b ? bb1 : bb0;
    int t = threadIdx.x;
    int row0 = blockIdx.x << 7;

    for (int i = t; i < 2048; i += 256) {
        int k = i >> 4, o = i & 15;
        ws[k * 32 + o] = w_nbr[i];
        ws[k * 32 + o + 16] = w_self[i];
    }
    const float4* x4 = (const float4*)x;
    for (int i = t; i < 4096; i += 256) {
        int r = i >> 5, c4 = i & 31;
        int row = row0 + r;
        float4 v = (row < N) ? x4[row * 32 + c4] : make_float4(0.f, 0.f, 0.f, 0.f);
        float* p = xs + r * 129 + c4 * 4;
        p[0] = v.x; p[1] = v.y; p[2] = v.z; p[3] = v.w;
    }
    __syncthreads();

    int og = t & 3;   // outs og*8 .. og*8+7
    int rg = t >> 2;  // rows 2rg, 2rg+1
    const float* xr0 = xs + (2 * rg) * 129;
    const float* xr1 = xs + (2 * rg + 1) * 129;
    const float* wp = ws + og * 8;

    unsigned long long a0 = 0, a1 = 0, a2 = 0, a3 = 0;
    unsigned long long a4 = 0, a5 = 0, a6 = 0, a7 = 0;
#pragma unroll 8
    for (int k = 0; k < 128; k++) {
        unsigned long long X0 = pk2(xr0[k], xr0[k]);
        unsigned long long X1 = pk2(xr1[k], xr1[k]);
        ulonglong2 wA = *(const ulonglong2*)(wp + k * 32);
        ulonglong2 wB = *(const ulonglong2*)(wp + k * 32 + 4);
        a0 = fma2(X0, wA.x, a0); a1 = fma2(X0, wA.y, a1);
        a2 = fma2(X0, wB.x, a2); a3 = fma2(X0, wB.y, a3);
        a4 = fma2(X1, wA.x, a4); a5 = fma2(X1, wA.y, a5);
        a6 = fma2(X1, wB.x, a6); a7 = fma2(X1, wB.y, a7);
    }

    int r0 = row0 + 2 * rg;
    int r1 = r0 + 1;
    if (og < 2) {  // y -> fp16
        int oy = og * 8;
#define EMIT_Y(ROW, A0, A1, A2, A3)                                          \
        if ((ROW) < N) {                                                     \
            float2 p0 = upk2(A0), p1 = upk2(A1), p2 = upk2(A2), p3 = upk2(A3);\
            __half2 h0 = __floats2half2_rn(p0.x, p0.y);                      \
            __half2 h1 = __floats2half2_rn(p1.x, p1.y);                      \
            __half2 h2 = __floats2half2_rn(p2.x, p2.y);                      \
            __half2 h3 = __floats2half2_rn(p3.x, p3.y);                      \
            uint4 hv;                                                        \
            hv.x = *(unsigned*)&h0; hv.y = *(unsigned*)&h1;                  \
            hv.z = *(unsigned*)&h2; hv.w = *(unsigned*)&h3;                  \
            *(uint4*)(g_yh[b] + (ROW) * 16 + oy) = hv;                       \
        }
        EMIT_Y(r0, a0, a1, a2, a3)
        EMIT_Y(r1, a4, a5, a6, a7)
#undef EMIT_Y
    } else {  // agg1 init = self + bias -> fp32
        int oa = og * 8 - 16;
        float4 b0 = *(const float4*)(bias + oa);
        float4 b1 = *(const float4*)(bias + oa + 4);
#define EMIT_A(ROW, A0, A1, A2, A3)                                          \
        if ((ROW) < N) {                                                     \
            float2 p0 = upk2(A0), p1 = upk2(A1), p2 = upk2(A2), p3 = upk2(A3);\
            float4 v0 = make_float4(p0.x + b0.x, p0.y + b0.y,                \
                                    p1.x + b0.z, p1.y + b0.w);               \
            float4 v1 = make_float4(p2.x + b1.x, p2.y + b1.y,                \
                                    p3.x + b1.z, p3.y + b1.w);               \
            *(float4*)(g_a1i[b] + (ROW) * 16 + oa) = v0;                     \
            *(float4*)(g_a1i[b] + (ROW) * 16 + oa + 4) = v1;                 \
        }
        EMIT_A(r0, a0, a1, a2, a3)
        EMIT_A(r1, a4, a5, a6, a7)
#undef EMIT_A
    }
}

// ---------------------------------------------------------------------------
// Gather aggregation: 2 lanes per node (16B half-rows), int4 index loads,
// fp16 pairwise-tree accumulation (groups of <=4 in fp16, then fp32 flush).
// Unrolled 8 edges / iter with two independent banks.
// PASS 0: agg1 = a1i + sum y[nbr]; h1f = relu(agg1) fp32; h1h = fp16
// PASS 1: agg2 = sum h1h[nbr]
// ---------------------------------------------------------------------------
template <int PASS>
__global__ void gather_kernel(int N) {
    int b = blockIdx.y;
    int t = threadIdx.x;
    int node = blockIdx.x * 128 + (t >> 1);
    if (node >= N) return;
    int h = t & 1;
    int cnt = g_cnt[b][node];
    if (cnt > CAP) cnt = CAP;
    const int* __restrict__ bkt = g_bkt[b] + (size_t)node * CAP;
    const __half* __restrict__ Y = PASS ? g_h1h[b] : g_yh[b];

    float2 c0 = make_float2(0.f, 0.f), c1 = c0, c2 = c0, c3 = c0;
    float2 d0 = c0, d1 = c0, d2 = c0, d3 = c0;

    // tree-sum 4 rows in fp16 (raw u32 lanes), flush to fp32 accumulators
#define TREE4(CACC0, CACC1, CACC2, CACC3, R0, R1, R2, R3)                     \
    {                                                                        \
        unsigned t0 = hadd2u(hadd2u(R0.x, R1.x), hadd2u(R2.x, R3.x));        \
        unsigned t1 = hadd2u(hadd2u(R0.y, R1.y), hadd2u(R2.y, R3.y));        \
        unsigned t2 = hadd2u(hadd2u(R0.z, R1.z), hadd2u(R2.z, R3.z));        \
        unsigned t3 = hadd2u(hadd2u(R0.w, R1.w), hadd2u(R2.w, R3.w));        \
        float2 f0 = h2f2(t0), f1 = h2f2(t1);                                 \
        float2 f2 = h2f2(t2), f3 = h2f2(t3);                                 \
        CACC0.x += f0.x; CACC0.y += f0.y; CACC1.x += f1.x; CACC1.y += f1.y;  \
        CACC2.x += f2.x; CACC2.y += f2.y; CACC3.x += f3.x; CACC3.y += f3.y;  \
    }

    int k = 0;
    for (; k + 7 < cnt; k += 8) {
        int4 sa = *(const int4*)(bkt + k);
        int4 sb = *(const int4*)(bkt + k + 4);
        uint4 rA = *(const uint4*)(Y + ((size_t)sa.x << 4) + (h << 3));
        uint4 rB = *(const uint4*)(Y + ((size_t)sa.y << 4) + (h << 3));
        uint4 rC = *(const uint4*)(Y + ((size_t)sa.z << 4) + (h << 3));
        uint4 rD = *(const uint4*)(Y + ((size_t)sa.w << 4) + (h << 3));
        uint4 rE = *(const uint4*)(Y + ((size_t)sb.x << 4) + (h << 3));
        uint4 rF = *(const uint4*)(Y + ((size_t)sb.y << 4) + (h << 3));
        uint4 rG = *(const uint4*)(Y + ((size_t)sb.z << 4) + (h << 3));
        uint4 rH = *(const uint4*)(Y + ((size_t)sb.w << 4) + (h << 3));
        TREE4(c0, c1, c2, c3, rA, rB, rC, rD)
        TREE4(d0, d1, d2, d3, rE, rF, rG, rH)
    }
    if (k + 3 < cnt) {
        int4 sa = *(const int4*)(bkt + k);
        uint4 rA = *(const uint4*)(Y + ((size_t)sa.x << 4) + (h << 3));
        uint4 rB = *(const uint4*)(Y + ((size_t)sa.y << 4) + (h << 3));
        uint4 rC = *(const uint4*)(Y + ((size_t)sa.z << 4) + (h << 3));
        uint4 rD = *(const uint4*)(Y + ((size_t)sa.w << 4) + (h << 3));
        TREE4(c0, c1, c2, c3, rA, rB, rC, rD)
        k += 4;
    }
#undef TREE4
    for (; k < cnt; k++) {
        int s = __ldg(bkt + k);
        uint4 raw = *(const uint4*)(Y + ((size_t)s << 4) + (h << 3));
        float2 f0 = h2f2(raw.x), f1 = h2f2(raw.y);
        float2 f2 = h2f2(raw.z), f3 = h2f2(raw.w);
        c0.x += f0.x; c0.y += f0.y; c1.x += f1.x; c1.y += f1.y;
        c2.x += f2.x; c2.y += f2.y; c3.x += f3.x; c3.y += f3.y;
    }
    c0.x += d0.x; c0.y += d0.y; c1.x += d1.x; c1.y += d1.y;
    c2.x += d2.x; c2.y += d2.y; c3.x += d3.x; c3.y += d3.y;

    size_t off = (size_t)node * 16 + (h << 3);
    if (PASS) {
        *(float4*)(g_agg2[b] + off) = make_float4(c0.x, c0.y, c1.x, c1.y);
        *(float4*)(g_agg2[b] + off + 4) = make_float4(c2.x, c2.y, c3.x, c3.y);
    } else {
        const float4* ip = (const float4*)(g_a1i[b] + off);
        float4 i0 = ip[0], i1 = ip[1];
        float4 v0 = make_float4(fmaxf(c0.x + i0.x, 0.f), fmaxf(c0.y + i0.y, 0.f),
                                fmaxf(c1.x + i0.z, 0.f), fmaxf(c1.y + i0.w, 0.f));
        float4 v1 = make_float4(fmaxf(c2.x + i1.x, 0.f), fmaxf(c2.y + i1.y, 0.f),
                                fmaxf(c3.x + i1.z, 0.f), fmaxf(c3.y + i1.w, 0.f));
        *(float4*)(g_h1f[b] + off) = v0;
        *(float4*)(g_h1f[b] + off + 4) = v1;
        __half2 q0 = __floats2half2_rn(v0.x, v0.y);
        __half2 q1 = __floats2half2_rn(v0.z, v0.w);
        __half2 q2 = __floats2half2_rn(v1.x, v1.y);
        __half2 q3 = __floats2half2_rn(v1.z, v1.w);
        uint4 hv;
        hv.x = *(unsigned*)&q0; hv.y = *(unsigned*)&q1;
        hv.z = *(unsigned*)&q2; hv.w = *(unsigned*)&q3;
        *(uint4*)(g_h1h[b] + off) = hv;
    }
}

// ---------------------------------------------------------------------------
// Fused tail: layer-2 convs (both branches) + MLP head, mol in registers.
// ---------------------------------------------------------------------------
__global__ __launch_bounds__(128)
void tail_kernel(const float* __restrict__ action,
                 const float* __restrict__ bp2, const float* __restrict__ bl2,
                 const float* __restrict__ b_in, const float* __restrict__ w_hid,
                 const float* __restrict__ b_hid, const float* __restrict__ w_out,
                 const float* __restrict__ b_out, float* __restrict__ out, int N) {
    __shared__ __align__(16) unsigned long long wsi[2][800];
    __shared__ __align__(16) float4 wst[1500];
    __shared__ __align__(16) float wh[700];
    __shared__ float bi[60];
    __shared__ float bs2[2][50];
    __shared__ __align__(16) float bh[12];
    __shared__ float wo[10];
    __shared__ float bo;
    int t = threadIdx.x;
    for (int i = t; i < 800; i += 128) {
        wsi[0][i] = g_wsi2[0][i];
        wsi[1][i] = g_wsi2[1][i];
    }
    for (int i = t; i < 1500; i += 128) wst[i] = g_wst[i];
    for (int i = t; i < 700; i += 128) wh[i] = w_hid[i];
    if (t < 60) bi[t] = b_in[t];
    if (t < 50) { bs2[0][t] = bp2[t]; bs2[1][t] = bl2[t]; }
    if (t < 10) { bh[t] = b_hid[t]; wo[t] = w_out[t]; }
    if (t == 0) bo = b_out[0];
    __syncthreads();

    int row = blockIdx.x * 128 + t;
    if (row >= N) return;

    unsigned long long molp[50];
#pragma unroll
    for (int b = 0; b < 2; b++) {
        unsigned long long ha[16];
        const float4* hp = (const float4*)(g_h1f[b] + (size_t)row * 16);
        const float4* ap = (const float4*)(g_agg2[b] + (size_t)row * 16);
#pragma unroll
        for (int q = 0; q < 4; q++) {
            float4 hv = hp[q], av = ap[q];
            ha[q * 4 + 0] = pk2(hv.x, av.x);
            ha[q * 4 + 1] = pk2(hv.y, av.y);
            ha[q * 4 + 2] = pk2(hv.z, av.z);
            ha[q * 4 + 3] = pk2(hv.w, av.w);
        }
        float prev = 0.f;
#pragma unroll 2
        for (int o = 0; o < 50; o++) {
            unsigned long long a0 = 0, a1 = 0;
#pragma unroll
            for (int k = 0; k < 16; k += 2) {
                a0 = fma2(ha[k], wsi[b][k * 50 + o], a0);
                a1 = fma2(ha[k + 1], wsi[b][(k + 1) * 50 + o], a1);
            }
            float2 p = upk2(a0), q = upk2(a1);
            float m = bs2[b][o] + ((p.x + p.y) + (q.x + q.y));
            if (o & 1) molp[(b * 50 + o) >> 1] = pk2(prev, m);
            else prev = m;
        }
    }

    unsigned long long pol2[5];
    const unsigned long long* bh2 = (const unsigned long long*)bh;
#pragma unroll
    for (int a = 0; a < 5; a++) pol2[a] = bh2[a];

#pragma unroll 1
    for (int o = 0; o < 60; o++) {
        const ulonglong2* wr = (const ulonglong2*)(wst + o * 25);
        unsigned long long a0 = 0, a1 = 0;
#pragma unroll
        for (int kk = 0; kk < 25; kk++) {
            ulonglong2 wv = wr[kk];
            a0 = fma2(molp[2 * kk], wv.x, a0);
            a1 = fma2(molp[2 * kk + 1], wv.y, a1);
        }
        float2 p = upk2(a0), q = upk2(a1);
        float f = fmaxf(bi[o] + ((p.x + p.y) + (q.x + q.y)), 0.f);
        unsigned long long f2 = pk2(f, f);
        const unsigned long long* whp = (const unsigned long long*)(wh + o * 10);
#pragma unroll
        for (int a = 0; a < 5; a++) pol2[a] = fma2(f2, whp[a], pol2[a]);
    }

    const unsigned long long* a2 = (const unsigned long long*)(action + (size_t)row * 10);
#pragma unroll
    for (int jj = 0; jj < 5; jj++) {
        float2 ap = upk2(a2[jj]);
        unsigned long long u = pk2(ap.x, ap.x);
        unsigned long long v = pk2(ap.y, ap.y);
        const unsigned long long* w1 = (const unsigned long long*)(wh + (60 + 2 * jj) * 10);
        const unsigned long long* w2p = (const unsigned long long*)(wh + (61 + 2 * jj) * 10);
#pragma unroll
        for (int a = 0; a < 5; a++) {
            pol2[a] = fma2(u, w1[a], pol2[a]);
            pol2[a] = fma2(v, w2p[a], pol2[a]);
        }
    }

    float res = bo;
#pragma unroll
    for (int a = 0; a < 5; a++) {
        float2 p = upk2(pol2[a]);
        res = fmaf(fmaxf(p.x, 0.f), wo[2 * a], res);
        res = fmaf(fmaxf(p.y, 0.f), wo[2 * a + 1], res);
    }
    out[row] = res;
}

// ---------------------------------------------------------------------------
// Side stream + fork/join events (created once at load).
// ---------------------------------------------------------------------------
static cudaStream_t g_s1 = 0;
static cudaEvent_t g_evRoot = 0, g_evCsr = 0;
static bool g_forkOk = false;
namespace {
struct ForkInit {
    ForkInit() {
        bool ok = true;
        ok &= (cudaStreamCreateWithFlags(&g_s1, cudaStreamNonBlocking) == cudaSuccess);
        ok &= (cudaEventCreateWithFlags(&g_evRoot, cudaEventDisableTiming) == cudaSuccess);
        ok &= (cudaEventCreateWithFlags(&g_evCsr, cudaEventDisableTiming) == cudaSuccess);
        g_forkOk = ok;
    }
};
static ForkInit g_forkInit;
}  // namespace

// ---------------------------------------------------------------------------
extern "C" void kernel_launch(void* const* d_in, const int* in_sizes, int n_in,
                              void* d_out, int out_size) {
    const float* px = (const float*)d_in[0];
    const int*   pe = (const int*)d_in[1];
    const float* lx = (const float*)d_in[2];
    const int*   le = (const int*)d_in[3];
    const float* action = (const float*)d_in[4];
    const float* wp1s = (const float*)d_in[5];
    const float* wp1n = (const float*)d_in[6];
    const float* bp1  = (const float*)d_in[7];
    const float* wp2s = (const float*)d_in[8];
    const float* wp2n = (const float*)d_in[9];
    const float* bp2  = (const float*)d_in[10];
    const float* wl1s = (const float*)d_in[11];
    const float* wl1n = (const float*)d_in[12];
    const float* bl1  = (const float*)d_in[13];
    const float* wl2s = (const float*)d_in[14];
    const float* wl2n = (const float*)d_in[15];
    const float* bl2  = (const float*)d_in[16];
    const float* w_in  = (const float*)d_in[17];
    const float* b_in  = (const float*)d_in[18];
    const float* w_hid = (const float*)d_in[19];
    const float* b_hid = (const float*)d_in[20];
    const float* w_out = (const float*)d_in[21];
    const float* b_out = (const float*)d_in[22];
    float* out = (float*)d_out;

    int N = in_sizes[0] / 128;
    int E0 = in_sizes[1] / 2;
    int E1 = in_sizes[3] / 2;
    int Em = (E0 > E1) ? E0 : E1;

    cudaStream_t sc = g_forkOk ? g_s1 : (cudaStream_t)0;  // bucket-arm stream
    if (g_forkOk) {
        cudaEventRecord(g_evRoot, 0);
        cudaStreamWaitEvent(g_s1, g_evRoot, 0);
    }

    // ---- dense arm (capture stream) -------------------------------------
    const int proj_smem = (128 * 129 + 128 * 32) * (int)sizeof(float);
    cudaFuncSetAttribute(proj_kernel, cudaFuncAttributeMaxDynamicSharedMemorySize,
                         proj_smem);
    dim3 gp((N + 127) / 128, 2);
    proj_kernel<<<gp, 256, proj_smem>>>(px, lx, wp1s, wl1s, wp1n, wl1n, bp1, bl1, N);

    // ---- bucket arm (side stream) ----------------------------------------
    prep_kernel<<<((2 * NN / 4) + 255) / 256, 256, 0, sc>>>(w_in, wp2s, wp2n,
                                                            wl2s, wl2n);
    dim3 ge((Em + 255) / 256, 2);
    bucket_kernel<<<ge, 256, 0, sc>>>(pe, pe + E0, le, le + E1, E0, E1);

    if (g_forkOk) {
        cudaEventRecord(g_evCsr, g_s1);
        cudaStreamWaitEvent(0, g_evCsr, 0);
    }

    // ---- joined: gathers + tail (capture stream) -------------------------
    dim3 gg((N + 127) / 128, 2);
    gather_kernel<0><<<gg, 256>>>(N);
    gather_kernel<1><<<gg, 256>>>(N);

    tail_kernel<<<(N + 127) / 128, 128>>>(action, bp2, bl2, b_in, w_hid, b_hid,
                                          w_out, b_out, out, N);
}

// round 14
// speedup vs baseline: 1.2078x; 1.0187x over previous
#include <cuda_runtime.h>
#include <cuda_fp16.h>

#define NN 100000
#define CAP 96

// ---------------------------------------------------------------------------
// Scratch (device globals — no allocation allowed)
// ---------------------------------------------------------------------------
__device__ __align__(16) __half g_yh[2][NN * 16];   // x @ w_nbr (fp16 payload)
__device__ __align__(16) float g_a1i[2][NN * 16];   // x @ w_self + b (init)
__device__ __align__(16) __half g_h1h[2][NN * 16];  // relu(agg1) fp16
__device__ __align__(16) float g_agg2[2][NN * 16];  // segsum(relu(agg1))
__device__ __align__(16) float4 g_wst[1500];        // transposed w_in [60][25] f4
__device__ __align__(16) unsigned long long g_wsi2[2][800];  // (w2s,w2n) packed
__device__ __align__(16) int g_cnt[2][NN];   // in-degree; zero-init at load,
                                             // re-zeroed by gather<1> each run
__device__ __align__(16) int g_bkt[2][NN * CAP];    // src ids bucketed by dst

// ---------------------------------------------------------------------------
// packed f32x2 / f16x2 helpers
// ---------------------------------------------------------------------------
static __device__ __forceinline__ unsigned long long pk2(float x, float y) {
    unsigned long long r;
    asm("mov.b64 %0, {%1,%2};" : "=l"(r) : "f"(x), "f"(y));
    return r;
}
static __device__ __forceinline__ float2 upk2(unsigned long long v) {
    float2 r;
    asm("mov.b64 {%0,%1}, %2;" : "=f"(r.x), "=f"(r.y) : "l"(v));
    return r;
}
static __device__ __forceinline__ unsigned long long fma2(
    unsigned long long a, unsigned long long b, unsigned long long c) {
    unsigned long long d;
    asm("fma.rn.f32x2 %0, %1, %2, %3;" : "=l"(d) : "l"(a), "l"(b), "l"(c));
    return d;
}
// fp16x2 add on raw 32-bit representation (nestable)
static __device__ __forceinline__ unsigned hadd2u(unsigned a, unsigned b) {
    unsigned r;
    asm("add.f16x2 %0, %1, %2;" : "=r"(r) : "r"(a), "r"(b));
    return r;
}
static __device__ __forceinline__ float2 h2f2(unsigned v) {
    return __half22float2(*(const __half2*)&v);
}

// ---------------------------------------------------------------------------
// Prep (side stream): pack/transpose small weights only.
// ---------------------------------------------------------------------------
__global__ void prep_kernel(const float* __restrict__ w_in,
                            const float* __restrict__ wp2s, const float* __restrict__ wp2n,
                            const float* __restrict__ wl2s, const float* __restrict__ wl2n) {
    int i = blockIdx.x * 256 + threadIdx.x;
    if (i < 1500) {
        int o = i / 25, kk = i % 25;
        float4 v;
        v.x = w_in[(kk * 4 + 0) * 60 + o];
        v.y = w_in[(kk * 4 + 1) * 60 + o];
        v.z = w_in[(kk * 4 + 2) * 60 + o];
        v.w = w_in[(kk * 4 + 3) * 60 + o];
        g_wst[i] = v;
    } else if (i < 2300) {
        int j = i - 1500;
        g_wsi2[0][j] = pk2(wp2s[j], wp2n[j]);
    } else if (i < 3100) {
        int j = i - 2300;
        g_wsi2[1][j] = pk2(wl2s[j], wl2n[j]);
    }
}

// ---------------------------------------------------------------------------
// Bucket build (single edge pass): slot = cnt[dst]++; bkt[dst][slot] = src.
// g_cnt is zero on entry (load-time init / zeroed by previous run's gather<1>).
// ---------------------------------------------------------------------------
__global__ void bucket_kernel(const int* __restrict__ s0, const int* __restrict__ d0,
                              const int* __restrict__ s1, const int* __restrict__ d1,
                              int E0, int E1) {
    int b = blockIdx.y;
    const int* src = b ? s1 : s0;
    const int* dst = b ? d1 : d0;
    int E = b ? E1 : E0;
    int e = blockIdx.x * 256 + threadIdx.x;
    if (e >= E) return;
    int d = dst[e];
    int slot = atomicAdd(&g_cnt[b][d], 1);
    if (slot < CAP) g_bkt[b][(size_t)d * CAP + slot] = src[e];
}

// ---------------------------------------------------------------------------
// Layer-1 projection, register-blocked (unchanged).
// ---------------------------------------------------------------------------
__global__ void proj_kernel(const float* __restrict__ x0, const float* __restrict__ x1,
                            const float* __restrict__ ws0, const float* __restrict__ ws1,
                            const float* __restrict__ wn0, const float* __restrict__ wn1,
                            const float* __restrict__ bb0, const float* __restrict__ bb1,
                            int N) {
    extern __shared__ float sm[];
    float* xs = sm;             // [128][129]
    float* ws = sm + 128 * 129; // [128][32]
    int b = blockIdx.y;
    const float* x = b ? x1 : x0;
    const float* w_self = b ? ws1 : ws0;
    const float* w_nbr = b ? wn1 : wn0;
    const float* bias = b ? bb1 : bb0;
    int t = threadIdx.x;
    int row0 = blockIdx.x << 7;

    for (int i = t; i < 2048; i += 256) {
        int k = i >> 4, o = i & 15;
        ws[k * 32 + o] = w_nbr[i];
        ws[k * 32 + o + 16] = w_self[i];
    }
    const float4* x4 = (const float4*)x;
    for (int i = t; i < 4096; i += 256) {
        int r = i >> 5, c4 = i & 31;
        int row = row0 + r;
        float4 v = (row < N) ? x4[row * 32 + c4] : make_float4(0.f, 0.f, 0.f, 0.f);
        float* p = xs + r * 129 + c4 * 4;
        p[0] = v.x; p[1] = v.y; p[2] = v.z; p[3] = v.w;
    }
    __syncthreads();

    int og = t & 3;   // outs og*8 .. og*8+7
    int rg = t >> 2;  // rows 2rg, 2rg+1
    const float* xr0 = xs + (2 * rg) * 129;
    const float* xr1 = xs + (2 * rg + 1) * 129;
    const float* wp = ws + og * 8;

    unsigned long long a0 = 0, a1 = 0, a2 = 0, a3 = 0;
    unsigned long long a4 = 0, a5 = 0, a6 = 0, a7 = 0;
#pragma unroll 8
    for (int k = 0; k < 128; k++) {
        unsigned long long X0 = pk2(xr0[k], xr0[k]);
        unsigned long long X1 = pk2(xr1[k], xr1[k]);
        ulonglong2 wA = *(const ulonglong2*)(wp + k * 32);
        ulonglong2 wB = *(const ulonglong2*)(wp + k * 32 + 4);
        a0 = fma2(X0, wA.x, a0); a1 = fma2(X0, wA.y, a1);
        a2 = fma2(X0, wB.x, a2); a3 = fma2(X0, wB.y, a3);
        a4 = fma2(X1, wA.x, a4); a5 = fma2(X1, wA.y, a5);
        a6 = fma2(X1, wB.x, a6); a7 = fma2(X1, wB.y, a7);
    }

    int r0 = row0 + 2 * rg;
    int r1 = r0 + 1;
    if (og < 2) {  // y -> fp16
        int oy = og * 8;
#define EMIT_Y(ROW, A0, A1, A2, A3)                                          \
        if ((ROW) < N) {                                                     \
            float2 p0 = upk2(A0), p1 = upk2(A1), p2 = upk2(A2), p3 = upk2(A3);\
            __half2 h0 = __floats2half2_rn(p0.x, p0.y);                      \
            __half2 h1 = __floats2half2_rn(p1.x, p1.y);                      \
            __half2 h2 = __floats2half2_rn(p2.x, p2.y);                      \
            __half2 h3 = __floats2half2_rn(p3.x, p3.y);                      \
            uint4 hv;                                                        \
            hv.x = *(unsigned*)&h0; hv.y = *(unsigned*)&h1;                  \
            hv.z = *(unsigned*)&h2; hv.w = *(unsigned*)&h3;                  \
            *(uint4*)(g_yh[b] + (ROW) * 16 + oy) = hv;                       \
        }
        EMIT_Y(r0, a0, a1, a2, a3)
        EMIT_Y(r1, a4, a5, a6, a7)
#undef EMIT_Y
    } else {  // agg1 init = self + bias -> fp32
        int oa = og * 8 - 16;
        float4 b0 = *(const float4*)(bias + oa);
        float4 b1 = *(const float4*)(bias + oa + 4);
#define EMIT_A(ROW, A0, A1, A2, A3)                                          \
        if ((ROW) < N) {                                                     \
            float2 p0 = upk2(A0), p1 = upk2(A1), p2 = upk2(A2), p3 = upk2(A3);\
            float4 v0 = make_float4(p0.x + b0.x, p0.y + b0.y,                \
                                    p1.x + b0.z, p1.y + b0.w);               \
            float4 v1 = make_float4(p2.x + b1.x, p2.y + b1.y,                \
                                    p3.x + b1.z, p3.y + b1.w);               \
            *(float4*)(g_a1i[b] + (ROW) * 16 + oa) = v0;                     \
            *(float4*)(g_a1i[b] + (ROW) * 16 + oa + 4) = v1;                 \
        }
        EMIT_A(r0, a0, a1, a2, a3)
        EMIT_A(r1, a4, a5, a6, a7)
#undef EMIT_A
    }
}

// ---------------------------------------------------------------------------
// Gather aggregation: 64-thread blocks (32 nodes) for fine-grained balance,
// 2 lanes per node (16B half-rows), int4 index loads, fp16 tree accumulation.
// PASS 0: agg1 = a1i + sum y[nbr]; h1h = fp16(relu(agg1))
// PASS 1: agg2 = sum h1h[nbr]; then zero g_cnt for the next run
// ---------------------------------------------------------------------------
template <int PASS>
__global__ __launch_bounds__(64)
void gather_kernel(int N) {
    int b = blockIdx.y;
    int t = threadIdx.x;
    int node = blockIdx.x * 32 + (t >> 1);
    if (node >= N) return;
    int h = t & 1;
    int cnt = g_cnt[b][node];
    if (cnt > CAP) cnt = CAP;
    const int* __restrict__ bkt = g_bkt[b] + (size_t)node * CAP;
    const __half* __restrict__ Yh =
        (PASS ? g_h1h[b] : g_yh[b]) + (h << 3);  // half-row base folded in

    float2 c0 = make_float2(0.f, 0.f), c1 = c0, c2 = c0, c3 = c0;
    float2 d0 = c0, d1 = c0, d2 = c0, d3 = c0;

    // tree-sum 4 rows in fp16 (raw u32 lanes), flush to fp32 accumulators
#define TREE4(CACC0, CACC1, CACC2, CACC3, R0, R1, R2, R3)                     \
    {                                                                        \
        unsigned t0 = hadd2u(hadd2u(R0.x, R1.x), hadd2u(R2.x, R3.x));        \
        unsigned t1 = hadd2u(hadd2u(R0.y, R1.y), hadd2u(R2.y, R3.y));        \
        unsigned t2 = hadd2u(hadd2u(R0.z, R1.z), hadd2u(R2.z, R3.z));        \
        unsigned t3 = hadd2u(hadd2u(R0.w, R1.w), hadd2u(R2.w, R3.w));        \
        float2 f0 = h2f2(t0), f1 = h2f2(t1);                                 \
        float2 f2 = h2f2(t2), f3 = h2f2(t3);                                 \
        CACC0.x += f0.x; CACC0.y += f0.y; CACC1.x += f1.x; CACC1.y += f1.y;  \
        CACC2.x += f2.x; CACC2.y += f2.y; CACC3.x += f3.x; CACC3.y += f3.y;  \
    }

    int k = 0;
    for (; k + 7 < cnt; k += 8) {
        int4 sa = *(const int4*)(bkt + k);
        int4 sb = *(const int4*)(bkt + k + 4);
        uint4 rA = *(const uint4*)(Yh + ((size_t)sa.x << 4));
        uint4 rB = *(const uint4*)(Yh + ((size_t)sa.y << 4));
        uint4 rC = *(const uint4*)(Yh + ((size_t)sa.z << 4));
        uint4 rD = *(const uint4*)(Yh + ((size_t)sa.w << 4));
        uint4 rE = *(const uint4*)(Yh + ((size_t)sb.x << 4));
        uint4 rF = *(const uint4*)(Yh + ((size_t)sb.y << 4));
        uint4 rG = *(const uint4*)(Yh + ((size_t)sb.z << 4));
        uint4 rH = *(const uint4*)(Yh + ((size_t)sb.w << 4));
        TREE4(c0, c1, c2, c3, rA, rB, rC, rD)
        TREE4(d0, d1, d2, d3, rE, rF, rG, rH)
    }
    if (k + 3 < cnt) {
        int4 sa = *(const int4*)(bkt + k);
        uint4 rA = *(const uint4*)(Yh + ((size_t)sa.x << 4));
        uint4 rB = *(const uint4*)(Yh + ((size_t)sa.y << 4));
        uint4 rC = *(const uint4*)(Yh + ((size_t)sa.z << 4));
        uint4 rD = *(const uint4*)(Yh + ((size_t)sa.w << 4));
        TREE4(c0, c1, c2, c3, rA, rB, rC, rD)
        k += 4;
    }
#undef TREE4
    for (; k < cnt; k++) {
        int s = __ldg(bkt + k);
        uint4 raw = *(const uint4*)(Yh + ((size_t)s << 4));
        float2 f0 = h2f2(raw.x), f1 = h2f2(raw.y);
        float2 f2 = h2f2(raw.z), f3 = h2f2(raw.w);
        c0.x += f0.x; c0.y += f0.y; c1.x += f1.x; c1.y += f1.y;
        c2.x += f2.x; c2.y += f2.y; c3.x += f3.x; c3.y += f3.y;
    }
    c0.x += d0.x; c0.y += d0.y; c1.x += d1.x; c1.y += d1.y;
    c2.x += d2.x; c2.y += d2.y; c3.x += d3.x; c3.y += d3.y;

    size_t off = (size_t)node * 16 + (h << 3);
    if (PASS) {
        *(float4*)(g_agg2[b] + off) = make_float4(c0.x, c0.y, c1.x, c1.y);
        *(float4*)(g_agg2[b] + off + 4) = make_float4(c2.x, c2.y, c3.x, c3.y);
        if (h == 0) g_cnt[b][node] = 0;  // reset for the next replay
    } else {
        const float4* ip = (const float4*)(g_a1i[b] + off);
        float4 i0 = ip[0], i1 = ip[1];
        __half2 q0 = __floats2half2_rn(fmaxf(c0.x + i0.x, 0.f),
                                       fmaxf(c0.y + i0.y, 0.f));
        __half2 q1 = __floats2half2_rn(fmaxf(c1.x + i0.z, 0.f),
                                       fmaxf(c1.y + i0.w, 0.f));
        __half2 q2 = __floats2half2_rn(fmaxf(c2.x + i1.x, 0.f),
                                       fmaxf(c2.y + i1.y, 0.f));
        __half2 q3 = __floats2half2_rn(fmaxf(c3.x + i1.z, 0.f),
                                       fmaxf(c3.y + i1.w, 0.f));
        uint4 hv;
        hv.x = *(unsigned*)&q0; hv.y = *(unsigned*)&q1;
        hv.z = *(unsigned*)&q2; hv.w = *(unsigned*)&q3;
        *(uint4*)(g_h1h[b] + off) = hv;
    }
}

// ---------------------------------------------------------------------------
// Fused tail: layer-2 convs (both branches) + MLP head, mol in registers.
// h1 read from fp16 g_h1h; agg2 fp32. Streaming, coalesced.
// ---------------------------------------------------------------------------
__global__ __launch_bounds__(128)
void tail_kernel(const float* __restrict__ action,
                 const float* __restrict__ bp2, const float* __restrict__ bl2,
                 const float* __restrict__ b_in, const float* __restrict__ w_hid,
                 const float* __restrict__ b_hid, const float* __restrict__ w_out,
                 const float* __restrict__ b_out, float* __restrict__ out, int N) {
    __shared__ __align__(16) unsigned long long wsi[2][800];
    __shared__ __align__(16) float4 wst[1500];
    __shared__ __align__(16) float wh[700];
    __shared__ float bi[60];
    __shared__ float bs2[2][50];
    __shared__ __align__(16) float bh[12];
    __shared__ float wo[10];
    __shared__ float bo;
    int t = threadIdx.x;
    for (int i = t; i < 800; i += 128) {
        wsi[0][i] = g_wsi2[0][i];
        wsi[1][i] = g_wsi2[1][i];
    }
    for (int i = t; i < 1500; i += 128) wst[i] = g_wst[i];
    for (int i = t; i < 700; i += 128) wh[i] = w_hid[i];
    if (t < 60) bi[t] = b_in[t];
    if (t < 50) { bs2[0][t] = bp2[t]; bs2[1][t] = bl2[t]; }
    if (t < 10) { bh[t] = b_hid[t]; wo[t] = w_out[t]; }
    if (t == 0) bo = b_out[0];
    __syncthreads();

    int row = blockIdx.x * 128 + t;
    if (row >= N) return;

    unsigned long long molp[50];
#pragma unroll
    for (int b = 0; b < 2; b++) {
        unsigned long long ha[16];
        const uint4* hp = (const uint4*)(g_h1h[b] + (size_t)row * 16);
        const float4* ap = (const float4*)(g_agg2[b] + (size_t)row * 16);
        uint4 H0 = hp[0], H1 = hp[1];
        float hv[16];
        {
            float2 f;
            f = h2f2(H0.x); hv[0] = f.x; hv[1] = f.y;
            f = h2f2(H0.y); hv[2] = f.x; hv[3] = f.y;
            f = h2f2(H0.z); hv[4] = f.x; hv[5] = f.y;
            f = h2f2(H0.w); hv[6] = f.x; hv[7] = f.y;
            f = h2f2(H1.x); hv[8] = f.x; hv[9] = f.y;
            f = h2f2(H1.y); hv[10] = f.x; hv[11] = f.y;
            f = h2f2(H1.z); hv[12] = f.x; hv[13] = f.y;
            f = h2f2(H1.w); hv[14] = f.x; hv[15] = f.y;
        }
#pragma unroll
        for (int q = 0; q < 4; q++) {
            float4 av = ap[q];
            ha[q * 4 + 0] = pk2(hv[q * 4 + 0], av.x);
            ha[q * 4 + 1] = pk2(hv[q * 4 + 1], av.y);
            ha[q * 4 + 2] = pk2(hv[q * 4 + 2], av.z);
            ha[q * 4 + 3] = pk2(hv[q * 4 + 3], av.w);
        }
        float prev = 0.f;
#pragma unroll 2
        for (int o = 0; o < 50; o++) {
            unsigned long long a0 = 0, a1 = 0;
#pragma unroll
            for (int k = 0; k < 16; k += 2) {
                a0 = fma2(ha[k], wsi[b][k * 50 + o], a0);
                a1 = fma2(ha[k + 1], wsi[b][(k + 1) * 50 + o], a1);
            }
            float2 p = upk2(a0), q = upk2(a1);
            float m = bs2[b][o] + ((p.x + p.y) + (q.x + q.y));
            if (o & 1) molp[(b * 50 + o) >> 1] = pk2(prev, m);
            else prev = m;
        }
    }

    unsigned long long pol2[5];
    const unsigned long long* bh2 = (const unsigned long long*)bh;
#pragma unroll
    for (int a = 0; a < 5; a++) pol2[a] = bh2[a];

#pragma unroll 1
    for (int o = 0; o < 60; o++) {
        const ulonglong2* wr = (const ulonglong2*)(wst + o * 25);
        unsigned long long a0 = 0, a1 = 0;
#pragma unroll
        for (int kk = 0; kk < 25; kk++) {
            ulonglong2 wv = wr[kk];
            a0 = fma2(molp[2 * kk], wv.x, a0);
            a1 = fma2(molp[2 * kk + 1], wv.y, a1);
        }
        float2 p = upk2(a0), q = upk2(a1);
        float f = fmaxf(bi[o] + ((p.x + p.y) + (q.x + q.y)), 0.f);
        unsigned long long f2 = pk2(f, f);
        const unsigned long long* whp = (const unsigned long long*)(wh + o * 10);
#pragma unroll
        for (int a = 0; a < 5; a++) pol2[a] = fma2(f2, whp[a], pol2[a]);
    }

    const unsigned long long* a2 = (const unsigned long long*)(action + (size_t)row * 10);
#pragma unroll
    for (int jj = 0; jj < 5; jj++) {
        float2 ap = upk2(a2[jj]);
        unsigned long long u = pk2(ap.x, ap.x);
        unsigned long long v = pk2(ap.y, ap.y);
        const unsigned long long* w1 = (const unsigned long long*)(wh + (60 + 2 * jj) * 10);
        const unsigned long long* w2p = (const unsigned long long*)(wh + (61 + 2 * jj) * 10);
#pragma unroll
        for (int a = 0; a < 5; a++) {
            pol2[a] = fma2(u, w1[a], pol2[a]);
            pol2[a] = fma2(v, w2p[a], pol2[a]);
        }
    }

    float res = bo;
#pragma unroll
    for (int a = 0; a < 5; a++) {
        float2 p = upk2(pol2[a]);
        res = fmaf(fmaxf(p.x, 0.f), wo[2 * a], res);
        res = fmaf(fmaxf(p.y, 0.f), wo[2 * a + 1], res);
    }
    out[row] = res;
}

// ---------------------------------------------------------------------------
// Side stream + fork/join events (created once at load).
// ---------------------------------------------------------------------------
static cudaStream_t g_s1 = 0;
static cudaEvent_t g_evRoot = 0, g_evCsr = 0;
static bool g_forkOk = false;
namespace {
struct ForkInit {
    ForkInit() {
        bool ok = true;
        ok &= (cudaStreamCreateWithFlags(&g_s1, cudaStreamNonBlocking) == cudaSuccess);
        ok &= (cudaEventCreateWithFlags(&g_evRoot, cudaEventDisableTiming) == cudaSuccess);
        ok &= (cudaEventCreateWithFlags(&g_evCsr, cudaEventDisableTiming) == cudaSuccess);
        g_forkOk = ok;
    }
};
static ForkInit g_forkInit;
}  // namespace

// ---------------------------------------------------------------------------
extern "C" void kernel_launch(void* const* d_in, const int* in_sizes, int n_in,
                              void* d_out, int out_size) {
    const float* px = (const float*)d_in[0];
    const int*   pe = (const int*)d_in[1];
    const float* lx = (const float*)d_in[2];
    const int*   le = (const int*)d_in[3];
    const float* action = (const float*)d_in[4];
    const float* wp1s = (const float*)d_in[5];
    const float* wp1n = (const float*)d_in[6];
    const float* bp1  = (const float*)d_in[7];
    const float* wp2s = (const float*)d_in[8];
    const float* wp2n = (const float*)d_in[9];
    const float* bp2  = (const float*)d_in[10];
    const float* wl1s = (const float*)d_in[11];
    const float* wl1n = (const float*)d_in[12];
    const float* bl1  = (const float*)d_in[13];
    const float* wl2s = (const float*)d_in[14];
    const float* wl2n = (const float*)d_in[15];
    const float* bl2  = (const float*)d_in[16];
    const float* w_in  = (const float*)d_in[17];
    const float* b_in  = (const float*)d_in[18];
    const float* w_hid = (const float*)d_in[19];
    const float* b_hid = (const float*)d_in[20];
    const float* w_out = (const float*)d_in[21];
    const float* b_out = (const float*)d_in[22];
    float* out = (float*)d_out;

    int N = in_sizes[0] / 128;
    int E0 = in_sizes[1] / 2;
    int E1 = in_sizes[3] / 2;
    int Em = (E0 > E1) ? E0 : E1;

    cudaStream_t sc = g_forkOk ? g_s1 : (cudaStream_t)0;  // bucket-arm stream
    if (g_forkOk) {
        cudaEventRecord(g_evRoot, 0);
        cudaStreamWaitEvent(g_s1, g_evRoot, 0);
    }

    // ---- dense arm (capture stream) -------------------------------------
    const int proj_smem = (128 * 129 + 128 * 32) * (int)sizeof(float);
    cudaFuncSetAttribute(proj_kernel, cudaFuncAttributeMaxDynamicSharedMemorySize,
                         proj_smem);
    dim3 gp((N + 127) / 128, 2);
    proj_kernel<<<gp, 256, proj_smem>>>(px, lx, wp1s, wl1s, wp1n, wl1n, bp1, bl1, N);

    // ---- bucket arm (side stream): bucket first (g_cnt pre-zeroed), prep after
    dim3 ge((Em + 255) / 256, 2);
    bucket_kernel<<<ge, 256, 0, sc>>>(pe, pe + E0, le, le + E1, E0, E1);
    prep_kernel<<<13, 256, 0, sc>>>(w_in, wp2s, wp2n, wl2s, wl2n);

    if (g_forkOk) {
        cudaEventRecord(g_evCsr, g_s1);
        cudaStreamWaitEvent(0, g_evCsr, 0);
    }

    // ---- joined: gathers + tail (capture stream) -------------------------
    dim3 gg((N + 31) / 32, 2);
    gather_kernel<0><<<gg, 64>>>(N);
    gather_kernel<1><<<gg, 64>>>(N);

    tail_kernel<<<(N + 127) / 128, 128>>>(action, bp2, bl2, b_in, w_hid, b_hid,
                                          w_out, b_out, out, N);
}

// round 15
// speedup vs baseline: 1.2417x; 1.0281x over previous
#include <cuda_runtime.h>
#include <cuda_fp16.h>

#define NN 100000
#define CAP 96

// ---------------------------------------------------------------------------
// Scratch (device globals — no allocation allowed)
// ---------------------------------------------------------------------------
__device__ __align__(16) __half g_yh[2][NN * 16];   // x @ w_nbr (fp16 payload)
__device__ __align__(16) float g_a1i[2][NN * 16];   // x @ w_self + b (init)
__device__ __align__(16) __half g_h1h[2][NN * 16];  // relu(agg1) fp16
__device__ __align__(16) __half g_a2h[2][NN * 16];  // segsum(relu(agg1)) fp16
__device__ __align__(16) float4 g_wst[1500];        // transposed w_in [60][25] f4
__device__ __align__(16) unsigned long long g_wsi2[2][800];  // (w2s,w2n) packed
__device__ __align__(16) int g_cnt[2][NN];   // in-degree; zero-init at load,
                                             // re-zeroed by gather<1> each run
__device__ __align__(16) int g_bkt[2][NN * CAP];    // src ids bucketed by dst

// ---------------------------------------------------------------------------
// packed f32x2 / f16x2 helpers
// ---------------------------------------------------------------------------
static __device__ __forceinline__ unsigned long long pk2(float x, float y) {
    unsigned long long r;
    asm("mov.b64 %0, {%1,%2};" : "=l"(r) : "f"(x), "f"(y));
    return r;
}
static __device__ __forceinline__ float2 upk2(unsigned long long v) {
    float2 r;
    asm("mov.b64 {%0,%1}, %2;" : "=f"(r.x), "=f"(r.y) : "l"(v));
    return r;
}
static __device__ __forceinline__ unsigned long long fma2(
    unsigned long long a, unsigned long long b, unsigned long long c) {
    unsigned long long d;
    asm("fma.rn.f32x2 %0, %1, %2, %3;" : "=l"(d) : "l"(a), "l"(b), "l"(c));
    return d;
}
// fp16x2 add on raw 32-bit representation (nestable)
static __device__ __forceinline__ unsigned hadd2u(unsigned a, unsigned b) {
    unsigned r;
    asm("add.f16x2 %0, %1, %2;" : "=r"(r) : "r"(a), "r"(b));
    return r;
}
static __device__ __forceinline__ float2 h2f2(unsigned v) {
    return __half22float2(*(const __half2*)&v);
}

// ---------------------------------------------------------------------------
// Prep (side stream): pack/transpose small weights only.
// ---------------------------------------------------------------------------
__global__ void prep_kernel(const float* __restrict__ w_in,
                            const float* __restrict__ wp2s, const float* __restrict__ wp2n,
                            const float* __restrict__ wl2s, const float* __restrict__ wl2n) {
    int i = blockIdx.x * 256 + threadIdx.x;
    if (i < 1500) {
        int o = i / 25, kk = i % 25;
        float4 v;
        v.x = w_in[(kk * 4 + 0) * 60 + o];
        v.y = w_in[(kk * 4 + 1) * 60 + o];
        v.z = w_in[(kk * 4 + 2) * 60 + o];
        v.w = w_in[(kk * 4 + 3) * 60 + o];
        g_wst[i] = v;
    } else if (i < 2300) {
        int j = i - 1500;
        g_wsi2[0][j] = pk2(wp2s[j], wp2n[j]);
    } else if (i < 3100) {
        int j = i - 2300;
        g_wsi2[1][j] = pk2(wl2s[j], wl2n[j]);
    }
}

// ---------------------------------------------------------------------------
// Bucket build (single edge pass): slot = cnt[dst]++; bkt[dst][slot] = src.
// g_cnt is zero on entry (load-time init / zeroed by previous run's gather<1>).
// ---------------------------------------------------------------------------
__global__ void bucket_kernel(const int* __restrict__ s0, const int* __restrict__ d0,
                              const int* __restrict__ s1, const int* __restrict__ d1,
                              int E0, int E1) {
    int b = blockIdx.y;
    const int* src = b ? s1 : s0;
    const int* dst = b ? d1 : d0;
    int E = b ? E1 : E0;
    int e = blockIdx.x * 256 + threadIdx.x;
    if (e >= E) return;
    int d = dst[e];
    int slot = atomicAdd(&g_cnt[b][d], 1);
    if (slot < CAP) g_bkt[b][(size_t)d * CAP + slot] = src[e];
}

// ---------------------------------------------------------------------------
// Layer-1 projection, register-blocked (unchanged).
// ---------------------------------------------------------------------------
__global__ void proj_kernel(const float* __restrict__ x0, const float* __restrict__ x1,
                            const float* __restrict__ ws0, const float* __restrict__ ws1,
                            const float* __restrict__ wn0, const float* __restrict__ wn1,
                            const float* __restrict__ bb0, const float* __restrict__ bb1,
                            int N) {
    extern __shared__ float sm[];
    float* xs = sm;             // [128][129]
    float* ws = sm + 128 * 129; // [128][32]
    int b = blockIdx.y;
    const float* x = b ? x1 : x0;
    const float* w_self = b ? ws1 : ws0;
    const float* w_nbr = b ? wn1 : wn0;
    const float* bias = b ? bb1 : bb0;
    int t = threadIdx.x;
    int row0 = blockIdx.x << 7;

    for (int i = t; i < 2048; i += 256) {
        int k = i >> 4, o = i & 15;
        ws[k * 32 + o] = w_nbr[i];
        ws[k * 32 + o + 16] = w_self[i];
    }
    const float4* x4 = (const float4*)x;
    for (int i = t; i < 4096; i += 256) {
        int r = i >> 5, c4 = i & 31;
        int row = row0 + r;
        float4 v = (row < N) ? x4[row * 32 + c4] : make_float4(0.f, 0.f, 0.f, 0.f);
        float* p = xs + r * 129 + c4 * 4;
        p[0] = v.x; p[1] = v.y; p[2] = v.z; p[3] = v.w;
    }
    __syncthreads();

    int og = t & 3;   // outs og*8 .. og*8+7
    int rg = t >> 2;  // rows 2rg, 2rg+1
    const float* xr0 = xs + (2 * rg) * 129;
    const float* xr1 = xs + (2 * rg + 1) * 129;
    const float* wp = ws + og * 8;

    unsigned long long a0 = 0, a1 = 0, a2 = 0, a3 = 0;
    unsigned long long a4 = 0, a5 = 0, a6 = 0, a7 = 0;
#pragma unroll 8
    for (int k = 0; k < 128; k++) {
        unsigned long long X0 = pk2(xr0[k], xr0[k]);
        unsigned long long X1 = pk2(xr1[k], xr1[k]);
        ulonglong2 wA = *(const ulonglong2*)(wp + k * 32);
        ulonglong2 wB = *(const ulonglong2*)(wp + k * 32 + 4);
        a0 = fma2(X0, wA.x, a0); a1 = fma2(X0, wA.y, a1);
        a2 = fma2(X0, wB.x, a2); a3 = fma2(X0, wB.y, a3);
        a4 = fma2(X1, wA.x, a4); a5 = fma2(X1, wA.y, a5);
        a6 = fma2(X1, wB.x, a6); a7 = fma2(X1, wB.y, a7);
    }

    int r0 = row0 + 2 * rg;
    int r1 = r0 + 1;
    if (og < 2) {  // y -> fp16
        int oy = og * 8;
#define EMIT_Y(ROW, A0, A1, A2, A3)                                          \
        if ((ROW) < N) {                                                     \
            float2 p0 = upk2(A0), p1 = upk2(A1), p2 = upk2(A2), p3 = upk2(A3);\
            __half2 h0 = __floats2half2_rn(p0.x, p0.y);                      \
            __half2 h1 = __floats2half2_rn(p1.x, p1.y);                      \
            __half2 h2 = __floats2half2_rn(p2.x, p2.y);                      \
            __half2 h3 = __floats2half2_rn(p3.x, p3.y);                      \
            uint4 hv;                                                        \
            hv.x = *(unsigned*)&h0; hv.y = *(unsigned*)&h1;                  \
            hv.z = *(unsigned*)&h2; hv.w = *(unsigned*)&h3;                  \
            *(uint4*)(g_yh[b] + (ROW) * 16 + oy) = hv;                       \
        }
        EMIT_Y(r0, a0, a1, a2, a3)
        EMIT_Y(r1, a4, a5, a6, a7)
#undef EMIT_Y
    } else {  // agg1 init = self + bias -> fp32
        int oa = og * 8 - 16;
        float4 b0 = *(const float4*)(bias + oa);
        float4 b1 = *(const float4*)(bias + oa + 4);
#define EMIT_A(ROW, A0, A1, A2, A3)                                          \
        if ((ROW) < N) {                                                     \
            float2 p0 = upk2(A0), p1 = upk2(A1), p2 = upk2(A2), p3 = upk2(A3);\
            float4 v0 = make_float4(p0.x + b0.x, p0.y + b0.y,                \
                                    p1.x + b0.z, p1.y + b0.w);               \
            float4 v1 = make_float4(p2.x + b1.x, p2.y + b1.y,                \
                                    p3.x + b1.z, p3.y + b1.w);               \
            *(float4*)(g_a1i[b] + (ROW) * 16 + oa) = v0;                     \
            *(float4*)(g_a1i[b] + (ROW) * 16 + oa + 4) = v1;                 \
        }
        EMIT_A(r0, a0, a1, a2, a3)
        EMIT_A(r1, a4, a5, a6, a7)
#undef EMIT_A
    }
}

// ---------------------------------------------------------------------------
// Gather aggregation: 64-thread blocks (32 nodes), 2 lanes per node (16B
// half-rows), int4 index loads, fp16 tree accumulation.
// PASS 0: agg1 = a1i + sum y[nbr]; h1h = fp16(relu(agg1))
// PASS 1: a2h = fp16(sum h1h[nbr]); then zero g_cnt for the next run
// ---------------------------------------------------------------------------
template <int PASS>
__global__ __launch_bounds__(64)
void gather_kernel(int N) {
    int b = blockIdx.y;
    int t = threadIdx.x;
    int node = blockIdx.x * 32 + (t >> 1);
    if (node >= N) return;
    int h = t & 1;
    int cnt = g_cnt[b][node];
    if (cnt > CAP) cnt = CAP;
    const int* __restrict__ bkt = g_bkt[b] + (size_t)node * CAP;
    const __half* __restrict__ Yh =
        (PASS ? g_h1h[b] : g_yh[b]) + (h << 3);  // half-row base folded in

    float2 c0 = make_float2(0.f, 0.f), c1 = c0, c2 = c0, c3 = c0;
    float2 d0 = c0, d1 = c0, d2 = c0, d3 = c0;

    // tree-sum 4 rows in fp16 (raw u32 lanes), flush to fp32 accumulators
#define TREE4(CACC0, CACC1, CACC2, CACC3, R0, R1, R2, R3)                     \
    {                                                                        \
        unsigned t0 = hadd2u(hadd2u(R0.x, R1.x), hadd2u(R2.x, R3.x));        \
        unsigned t1 = hadd2u(hadd2u(R0.y, R1.y), hadd2u(R2.y, R3.y));        \
        unsigned t2 = hadd2u(hadd2u(R0.z, R1.z), hadd2u(R2.z, R3.z));        \
        unsigned t3 = hadd2u(hadd2u(R0.w, R1.w), hadd2u(R2.w, R3.w));        \
        float2 f0 = h2f2(t0), f1 = h2f2(t1);                                 \
        float2 f2 = h2f2(t2), f3 = h2f2(t3);                                 \
        CACC0.x += f0.x; CACC0.y += f0.y; CACC1.x += f1.x; CACC1.y += f1.y;  \
        CACC2.x += f2.x; CACC2.y += f2.y; CACC3.x += f3.x; CACC3.y += f3.y;  \
    }

    int k = 0;
    for (; k + 7 < cnt; k += 8) {
        int4 sa = *(const int4*)(bkt + k);
        int4 sb = *(const int4*)(bkt + k + 4);
        uint4 rA = *(const uint4*)(Yh + ((size_t)sa.x << 4));
        uint4 rB = *(const uint4*)(Yh + ((size_t)sa.y << 4));
        uint4 rC = *(const uint4*)(Yh + ((size_t)sa.z << 4));
        uint4 rD = *(const uint4*)(Yh + ((size_t)sa.w << 4));
        uint4 rE = *(const uint4*)(Yh + ((size_t)sb.x << 4));
        uint4 rF = *(const uint4*)(Yh + ((size_t)sb.y << 4));
        uint4 rG = *(const uint4*)(Yh + ((size_t)sb.z << 4));
        uint4 rH = *(const uint4*)(Yh + ((size_t)sb.w << 4));
        TREE4(c0, c1, c2, c3, rA, rB, rC, rD)
        TREE4(d0, d1, d2, d3, rE, rF, rG, rH)
    }
    if (k + 3 < cnt) {
        int4 sa = *(const int4*)(bkt + k);
        uint4 rA = *(const uint4*)(Yh + ((size_t)sa.x << 4));
        uint4 rB = *(const uint4*)(Yh + ((size_t)sa.y << 4));
        uint4 rC = *(const uint4*)(Yh + ((size_t)sa.z << 4));
        uint4 rD = *(const uint4*)(Yh + ((size_t)sa.w << 4));
        TREE4(c0, c1, c2, c3, rA, rB, rC, rD)
        k += 4;
    }
#undef TREE4
    for (; k < cnt; k++) {
        int s = __ldg(bkt + k);
        uint4 raw = *(const uint4*)(Yh + ((size_t)s << 4));
        float2 f0 = h2f2(raw.x), f1 = h2f2(raw.y);
        float2 f2 = h2f2(raw.z), f3 = h2f2(raw.w);
        c0.x += f0.x; c0.y += f0.y; c1.x += f1.x; c1.y += f1.y;
        c2.x += f2.x; c2.y += f2.y; c3.x += f3.x; c3.y += f3.y;
    }
    c0.x += d0.x; c0.y += d0.y; c1.x += d1.x; c1.y += d1.y;
    c2.x += d2.x; c2.y += d2.y; c3.x += d3.x; c3.y += d3.y;

    size_t off = (size_t)node * 16 + (h << 3);
    if (PASS) {
        __half2 q0 = __floats2half2_rn(c0.x, c0.y);
        __half2 q1 = __floats2half2_rn(c1.x, c1.y);
        __half2 q2 = __floats2half2_rn(c2.x, c2.y);
        __half2 q3 = __floats2half2_rn(c3.x, c3.y);
        uint4 hv;
        hv.x = *(unsigned*)&q0; hv.y = *(unsigned*)&q1;
        hv.z = *(unsigned*)&q2; hv.w = *(unsigned*)&q3;
        *(uint4*)(g_a2h[b] + off) = hv;
        if (h == 0) g_cnt[b][node] = 0;  // reset for the next replay
    } else {
        const float4* ip = (const float4*)(g_a1i[b] + off);
        float4 i0 = ip[0], i1 = ip[1];
        __half2 q0 = __floats2half2_rn(fmaxf(c0.x + i0.x, 0.f),
                                       fmaxf(c0.y + i0.y, 0.f));
        __half2 q1 = __floats2half2_rn(fmaxf(c1.x + i0.z, 0.f),
                                       fmaxf(c1.y + i0.w, 0.f));
        __half2 q2 = __floats2half2_rn(fmaxf(c2.x + i1.x, 0.f),
                                       fmaxf(c2.y + i1.y, 0.f));
        __half2 q3 = __floats2half2_rn(fmaxf(c3.x + i1.z, 0.f),
                                       fmaxf(c3.y + i1.w, 0.f));
        uint4 hv;
        hv.x = *(unsigned*)&q0; hv.y = *(unsigned*)&q1;
        hv.z = *(unsigned*)&q2; hv.w = *(unsigned*)&q3;
        *(uint4*)(g_h1h[b] + off) = hv;
    }
}

// ---------------------------------------------------------------------------
// Fused tail: layer-2 convs (both branches) + MLP head, mol in registers.
// 256 threads/block (same 40KB smem serves 2x rows -> ~2x occupancy).
// h1 and agg2 both read as fp16 uint4 (32B/row each).
// ---------------------------------------------------------------------------
__global__ __launch_bounds__(256)
void tail_kernel(const float* __restrict__ action,
                 const float* __restrict__ bp2, const float* __restrict__ bl2,
                 const float* __restrict__ b_in, const float* __restrict__ w_hid,
                 const float* __restrict__ b_hid, const float* __restrict__ w_out,
                 const float* __restrict__ b_out, float* __restrict__ out, int N) {
    __shared__ __align__(16) unsigned long long wsi[2][800];
    __shared__ __align__(16) float4 wst[1500];
    __shared__ __align__(16) float wh[700];
    __shared__ float bi[60];
    __shared__ float bs2[2][50];
    __shared__ __align__(16) float bh[12];
    __shared__ float wo[10];
    __shared__ float bo;
    int t = threadIdx.x;
    for (int i = t; i < 800; i += 256) {
        wsi[0][i] = g_wsi2[0][i];
        wsi[1][i] = g_wsi2[1][i];
    }
    for (int i = t; i < 1500; i += 256) wst[i] = g_wst[i];
    for (int i = t; i < 700; i += 256) wh[i] = w_hid[i];
    if (t < 60) bi[t] = b_in[t];
    if (t < 50) { bs2[0][t] = bp2[t]; bs2[1][t] = bl2[t]; }
    if (t < 10) { bh[t] = b_hid[t]; wo[t] = w_out[t]; }
    if (t == 0) bo = b_out[0];
    __syncthreads();

    int row = blockIdx.x * 256 + t;
    if (row >= N) return;

    unsigned long long molp[50];
#pragma unroll
    for (int b = 0; b < 2; b++) {
        unsigned long long ha[16];
        const uint4* hp = (const uint4*)(g_h1h[b] + (size_t)row * 16);
        const uint4* ap = (const uint4*)(g_a2h[b] + (size_t)row * 16);
        uint4 H0 = hp[0], H1 = hp[1];
        uint4 A0 = ap[0], A1 = ap[1];
#define HA2(J, HW, AW)                                                        \
        {                                                                    \
            float2 fh = h2f2(HW), fa = h2f2(AW);                             \
            ha[(J) * 2 + 0] = pk2(fh.x, fa.x);                               \
            ha[(J) * 2 + 1] = pk2(fh.y, fa.y);                               \
        }
        HA2(0, H0.x, A0.x) HA2(1, H0.y, A0.y)
        HA2(2, H0.z, A0.z) HA2(3, H0.w, A0.w)
        HA2(4, H1.x, A1.x) HA2(5, H1.y, A1.y)
        HA2(6, H1.z, A1.z) HA2(7, H1.w, A1.w)
#undef HA2
        float prev = 0.f;
#pragma unroll 2
        for (int o = 0; o < 50; o++) {
            unsigned long long a0 = 0, a1 = 0;
#pragma unroll
            for (int k = 0; k < 16; k += 2) {
                a0 = fma2(ha[k], wsi[b][k * 50 + o], a0);
                a1 = fma2(ha[k + 1], wsi[b][(k + 1) * 50 + o], a1);
            }
            float2 p = upk2(a0), q = upk2(a1);
            float m = bs2[b][o] + ((p.x + p.y) + (q.x + q.y));
            if (o & 1) molp[(b * 50 + o) >> 1] = pk2(prev, m);
            else prev = m;
        }
    }

    unsigned long long pol2[5];
    const unsigned long long* bh2 = (const unsigned long long*)bh;
#pragma unroll
    for (int a = 0; a < 5; a++) pol2[a] = bh2[a];

#pragma unroll 1
    for (int o = 0; o < 60; o++) {
        const ulonglong2* wr = (const ulonglong2*)(wst + o * 25);
        unsigned long long a0 = 0, a1 = 0;
#pragma unroll
        for (int kk = 0; kk < 25; kk++) {
            ulonglong2 wv = wr[kk];
            a0 = fma2(molp[2 * kk], wv.x, a0);
            a1 = fma2(molp[2 * kk + 1], wv.y, a1);
        }
        float2 p = upk2(a0), q = upk2(a1);
        float f = fmaxf(bi[o] + ((p.x + p.y) + (q.x + q.y)), 0.f);
        unsigned long long f2 = pk2(f, f);
        const unsigned long long* whp = (const unsigned long long*)(wh + o * 10);
#pragma unroll
        for (int a = 0; a < 5; a++) pol2[a] = fma2(f2, whp[a], pol2[a]);
    }

    const unsigned long long* a2 = (const unsigned long long*)(action + (size_t)row * 10);
#pragma unroll
    for (int jj = 0; jj < 5; jj++) {
        float2 ap = upk2(a2[jj]);
        unsigned long long u = pk2(ap.x, ap.x);
        unsigned long long v = pk2(ap.y, ap.y);
        const unsigned long long* w1 = (const unsigned long long*)(wh + (60 + 2 * jj) * 10);
        const unsigned long long* w2p = (const unsigned long long*)(wh + (61 + 2 * jj) * 10);
#pragma unroll
        for (int a = 0; a < 5; a++) {
            pol2[a] = fma2(u, w1[a], pol2[a]);
            pol2[a] = fma2(v, w2p[a], pol2[a]);
        }
    }

    float res = bo;
#pragma unroll
    for (int a = 0; a < 5; a++) {
        float2 p = upk2(pol2[a]);
        res = fmaf(fmaxf(p.x, 0.f), wo[2 * a], res);
        res = fmaf(fmaxf(p.y, 0.f), wo[2 * a + 1], res);
    }
    out[row] = res;
}

// ---------------------------------------------------------------------------
// Side stream + fork/join events (created once at load).
// ---------------------------------------------------------------------------
static cudaStream_t g_s1 = 0;
static cudaEvent_t g_evRoot = 0, g_evCsr = 0;
static bool g_forkOk = false;
namespace {
struct ForkInit {
    ForkInit() {
        bool ok = true;
        ok &= (cudaStreamCreateWithFlags(&g_s1, cudaStreamNonBlocking) == cudaSuccess);
        ok &= (cudaEventCreateWithFlags(&g_evRoot, cudaEventDisableTiming) == cudaSuccess);
        ok &= (cudaEventCreateWithFlags(&g_evCsr, cudaEventDisableTiming) == cudaSuccess);
        g_forkOk = ok;
    }
};
static ForkInit g_forkInit;
}  // namespace

// ---------------------------------------------------------------------------
extern "C" void kernel_launch(void* const* d_in, const int* in_sizes, int n_in,
                              void* d_out, int out_size) {
    const float* px = (const float*)d_in[0];
    const int*   pe = (const int*)d_in[1];
    const float* lx = (const float*)d_in[2];
    const int*   le = (const int*)d_in[3];
    const float* action = (const float*)d_in[4];
    const float* wp1s = (const float*)d_in[5];
    const float* wp1n = (const float*)d_in[6];
    const float* bp1  = (const float*)d_in[7];
    const float* wp2s = (const float*)d_in[8];
    const float* wp2n = (const float*)d_in[9];
    const float* bp2  = (const float*)d_in[10];
    const float* wl1s = (const float*)d_in[11];
    const float* wl1n = (const float*)d_in[12];
    const float* bl1  = (const float*)d_in[13];
    const float* wl2s = (const float*)d_in[14];
    const float* wl2n = (const float*)d_in[15];
    const float* bl2  = (const float*)d_in[16];
    const float* w_in  = (const float*)d_in[17];
    const float* b_in  = (const float*)d_in[18];
    const float* w_hid = (const float*)d_in[19];
    const float* b_hid = (const float*)d_in[20];
    const float* w_out = (const float*)d_in[21];
    const float* b_out = (const float*)d_in[22];
    float* out = (float*)d_out;

    int N = in_sizes[0] / 128;
    int E0 = in_sizes[1] / 2;
    int E1 = in_sizes[3] / 2;
    int Em = (E0 > E1) ? E0 : E1;

    cudaStream_t sc = g_forkOk ? g_s1 : (cudaStream_t)0;  // bucket-arm stream
    if (g_forkOk) {
        cudaEventRecord(g_evRoot, 0);
        cudaStreamWaitEvent(g_s1, g_evRoot, 0);
    }

    // ---- dense arm (capture stream) -------------------------------------
    const int proj_smem = (128 * 129 + 128 * 32) * (int)sizeof(float);
    cudaFuncSetAttribute(proj_kernel, cudaFuncAttributeMaxDynamicSharedMemorySize,
                         proj_smem);
    dim3 gp((N + 127) / 128, 2);
    proj_kernel<<<gp, 256, proj_smem>>>(px, lx, wp1s, wl1s, wp1n, wl1n, bp1, bl1, N);

    // ---- bucket arm (side stream): bucket first (g_cnt pre-zeroed), prep after
    dim3 ge((Em + 255) / 256, 2);
    bucket_kernel<<<ge, 256, 0, sc>>>(pe, pe + E0, le, le + E1, E0, E1);
    prep_kernel<<<13, 256, 0, sc>>>(w_in, wp2s, wp2n, wl2s, wl2n);

    if (g_forkOk) {
        cudaEventRecord(g_evCsr, g_s1);
        cudaStreamWaitEvent(0, g_evCsr, 0);
    }

    // ---- joined: gathers + tail (capture stream) -------------------------
    dim3 gg((N + 31) / 32, 2);
    gather_kernel<0><<<gg, 64>>>(N);
    gather_kernel<1><<<gg, 64>>>(N);

    tail_kernel<<<(N + 255) / 256, 256>>>(action, bp2, bl2, b_in, w_hid, b_hid,
                                          w_out, b_out, out, N);
}